// round 11
// baseline (speedup 1.0000x reference)
#include <cuda_runtime.h>
#include <cuda_bf16.h>
#include <cstdint>

#define NMAX 50000
#define EMAX 800000
#define HD 128
#define NG 128
#define NCLS 10
#define BPAD 136                      // padded row stride (bf16 elems), 272B: conflict-free ldmatrix
#define EB 128                        // edges staged per block (fallback path)

// ---------------- scratch (device globals; no runtime allocation) -----------
// NOTE: referenced ONLY from device code (selected via int selectors).
// Host-passed &g_x* resolves to host shadow memory (NVLink-C2C, 15-22x slow).
// Harness pointers (d_in[i]) are true device pointers and safe as kernel args.
__device__ float g_xA[NMAX * HD];
__device__ float g_xB[NMAX * HD];
__device__ float g_agg[NMAX * HD];   // fallback (atomic) path only
__device__ float g_h1[NMAX * HD];
__device__ __nv_bfloat16 g_Ahi[NMAX * HD];   // prefused A = x + nc*agg, hi part
__device__ __nv_bfloat16 g_Alo[NMAX * HD];   // lo part (error compensation)
__device__ float g_stats[2 * HD];   // [0:128) col sums, [128:256) col sumsq
__device__ float g_pool[NG * HD];
__device__ float g_cnt[NG];
__device__ int   g_idx64;           // 1 if indices are int64, 0 if int32
// CSR of the (static) edge set, built once per call; (src, w) packed as int2
__device__ int   g_deg[NMAX + 1];
__device__ int   g_off[NMAX + 1];
__device__ int   g_cursor[NMAX];
__device__ int   g_bsum[128];
__device__ int2  g_csr[EMAX];
// pre-split weights in the padded SMEM image: [k][n], row stride BPAD
__device__ __nv_bfloat16 g_Whi[6][HD * BPAD];
__device__ __nv_bfloat16 g_Wlo[6][HD * BPAD];

// ---------------- helpers -----------------------------------------------------
__device__ __forceinline__ uint32_t smem_u32(const void* p) {
    uint32_t a;
    asm("{ .reg .u64 t; cvta.to.shared.u64 t, %1; cvt.u32.u64 %0, t; }"
        : "=r"(a) : "l"(p));
    return a;
}
__device__ __forceinline__ void red_add_v4(float* p, float4 v) {
    asm volatile("red.global.add.v4.f32 [%0], {%1,%2,%3,%4};"
                 :: "l"(p), "f"(v.x), "f"(v.y), "f"(v.z), "f"(v.w)
                 : "memory");
}
__device__ __forceinline__ uint32_t pack_bf(__nv_bfloat16 a, __nv_bfloat16 b) {
    uint16_t ua = *(uint16_t*)&a, ub = *(uint16_t*)&b;
    return (uint32_t)ua | ((uint32_t)ub << 16);
}
__device__ __forceinline__ void split4(float a0, float a1, float a2, float a3,
                                       uint2& hp, uint2& lp) {
    __nv_bfloat16 h0 = __float2bfloat16(a0);
    __nv_bfloat16 h1 = __float2bfloat16(a1);
    __nv_bfloat16 h2 = __float2bfloat16(a2);
    __nv_bfloat16 h3 = __float2bfloat16(a3);
    __nv_bfloat16 l0 = __float2bfloat16(a0 - __bfloat162float(h0));
    __nv_bfloat16 l1 = __float2bfloat16(a1 - __bfloat162float(h1));
    __nv_bfloat16 l2 = __float2bfloat16(a2 - __bfloat162float(h2));
    __nv_bfloat16 l3 = __float2bfloat16(a3 - __bfloat162float(h3));
    hp.x = pack_bf(h0, h1); hp.y = pack_bf(h2, h3);
    lp.x = pack_bf(l0, l1); lp.y = pack_bf(l2, l3);
}
__device__ __forceinline__ void ldmatrix_x4(uint32_t* r, uint32_t addr) {
    asm volatile("ldmatrix.sync.aligned.m8n8.x4.shared.b16 {%0,%1,%2,%3}, [%4];"
                 : "=r"(r[0]), "=r"(r[1]), "=r"(r[2]), "=r"(r[3]) : "r"(addr));
}
__device__ __forceinline__ void ldmatrix_x4_trans(uint32_t* r, uint32_t addr) {
    asm volatile("ldmatrix.sync.aligned.m8n8.x4.trans.shared.b16 {%0,%1,%2,%3}, [%4];"
                 : "=r"(r[0]), "=r"(r[1]), "=r"(r[2]), "=r"(r[3]) : "r"(addr));
}
__device__ __forceinline__ void mma_bf16(float* c, const uint32_t* a, const uint32_t* b) {
    asm volatile(
        "mma.sync.aligned.m16n8k16.row.col.f32.bf16.bf16.f32 "
        "{%0,%1,%2,%3}, {%4,%5,%6,%7}, {%8,%9}, {%0,%1,%2,%3};"
        : "+f"(c[0]), "+f"(c[1]), "+f"(c[2]), "+f"(c[3])
        : "r"(a[0]), "r"(a[1]), "r"(a[2]), "r"(a[3]), "r"(b[0]), "r"(b[1]));
}
__device__ __forceinline__ long long load_index(const void* base, long long off, int is64) {
    if (is64) return ((const long long*)base)[off];
    return (long long)((const int*)base)[off];
}
// layer input select: sel<0 -> external harness pointer, 0 -> g_xA, 1 -> g_xB
__device__ __forceinline__ const float* pick_x(int sel, const float* xext) {
    if (sel < 0) return xext;
    return sel ? g_xB : g_xA;
}

// ---------------- small utility kernels --------------------------------------
__global__ void zero_stats_pool_kernel(int n) {
    int i = blockIdx.x * blockDim.x + threadIdx.x;
    if (i < 2 * HD) g_stats[i] = 0.f;
    if (i < NG * HD) g_pool[i] = 0.f;
    if (i < NG) g_cnt[i] = 0.f;
}
__global__ void zero_agg_stats_kernel(int n4) {   // fallback path only
    int i = blockIdx.x * blockDim.x + threadIdx.x;
    if (i < 2 * HD) g_stats[i] = 0.f;
    float4 z = make_float4(0.f, 0.f, 0.f, 0.f);
    float4* a = reinterpret_cast<float4*>(g_agg);
    for (int j = i; j < n4; j += gridDim.x * blockDim.x) a[j] = z;
}

// ---------------- weight pre-split + idx detect + deg zero (one launch) --------
__global__ void conv_w_all_kernel(const float* __restrict__ W1,
                                  const float* __restrict__ W2,
                                  const void* __restrict__ ei, int E, int n_nodes) {
    int i = blockIdx.x * blockDim.x + threadIdx.x;
    if (i == 0) {           // fold index-dtype detection into this launch
        const long long* p64 = (const long long*)ei;
        int ok64 = 1;
        for (int t = 0; t < 16; t++) {
            long long v = p64[t];
            if (v < 0 || v >= (long long)n_nodes) { ok64 = 0; break; }
        }
        if (ok64) {
            for (int t = 0; t < 16; t++) {
                long long v = p64[(size_t)E + t];
                if (v < 0 || v >= (long long)n_nodes) { ok64 = 0; break; }
            }
        }
        g_idx64 = ok64;
    }
    if (i <= n_nodes) g_deg[i] = 0;      // fold degree-array zeroing
    if (i >= 6 * HD * HD) return;
    int slot = i >> 14;
    int j = i & (HD * HD - 1);
    int n = j & 127, k = j >> 7;
    const float* W = (slot < 3) ? (W1 + (size_t)slot * HD * HD)
                                : (W2 + (size_t)(slot - 3) * HD * HD);
    float w = W[k * HD + n];
    __nv_bfloat16 hi = __float2bfloat16(w);
    float lof = w - __bfloat162float(hi);
    g_Whi[slot][k * BPAD + n] = hi;
    g_Wlo[slot][k * BPAD + n] = __float2bfloat16(lof);
}

// ---------------- CSR construction (once per call) -----------------------------
__global__ void hist_kernel(const void* __restrict__ ei, int E) {
    int is64 = g_idx64;
    for (long long e = blockIdx.x * blockDim.x + threadIdx.x; e < E;
         e += (long long)gridDim.x * blockDim.x) {
        int d = (int)load_index(ei, (long long)E + e, is64);
        atomicAdd(&g_deg[d], 1);
    }
}
__global__ void scan1_kernel(int n) {
    __shared__ int sh[512];
    int t = threadIdx.x;
    int i = blockIdx.x * 512 + t;
    int v = (i < n) ? g_deg[i] : 0;
    sh[t] = v;
    __syncthreads();
#pragma unroll
    for (int o = 1; o < 512; o <<= 1) {
        int tmp = (t >= o) ? sh[t - o] : 0;
        __syncthreads();
        sh[t] += tmp;
        __syncthreads();
    }
    if (i < n) g_off[i] = sh[t] - v;        // exclusive within chunk
    if (t == 511) g_bsum[blockIdx.x] = sh[511];
}
__global__ void scan2_kernel(int nchunks, int E, int n) {
    __shared__ int sh[512];
    int t = threadIdx.x;
    int v = (t < nchunks) ? g_bsum[t] : 0;
    sh[t] = v;
    __syncthreads();
#pragma unroll
    for (int o = 1; o < 512; o <<= 1) {
        int tmp = (t >= o) ? sh[t - o] : 0;
        __syncthreads();
        sh[t] += tmp;
        __syncthreads();
    }
    if (t < nchunks) g_bsum[t] = sh[t] - v; // exclusive chunk offsets
    if (t == 0) g_off[n] = E;
}
__global__ void scan3_kernel(int n) {
    int i = blockIdx.x * blockDim.x + threadIdx.x;
    if (i < n) {
        int o = g_off[i] + g_bsum[i >> 9];
        g_off[i] = o;
        g_cursor[i] = o;
    }
}
__global__ void scatter_kernel(const void* __restrict__ ei,
                               const float* __restrict__ ec, int E) {
    int is64 = g_idx64;
    for (long long e = blockIdx.x * blockDim.x + threadIdx.x; e < E;
         e += (long long)gridDim.x * blockDim.x) {
        int s = (int)load_index(ei, e, is64);
        int d = (int)load_index(ei, (long long)E + e, is64);
        float w = __ldg(ec + e);
        int pos = atomicAdd(&g_cursor[d], 1);
        g_csr[pos] = make_int2(s, __float_as_int(w));
    }
}

// ---------------- CSR aggregation + A prefusion --------------------------------
// Warp per node; 8-wide batched gathers; fuses A = x + nc*agg, splits bf16
// hi/lo, writes g_Ahi/g_Alo directly. Block 0 also resets g_stats for the
// coming tgemm<0> (previous tgemm<1> consumers already finished, stream order).
__global__ __launch_bounds__(256, 4)
void csr_agg_kernel(int n, int sel, const float* __restrict__ xext,
                    const float* __restrict__ nc) {
    if (blockIdx.x == 0 && threadIdx.x < 2 * HD) g_stats[threadIdx.x] = 0.f;
    int v = blockIdx.x * 8 + (threadIdx.x >> 5);
    if (v >= n) return;
    int lane = threadIdx.x & 31;
    const float* x = pick_x(sel, xext);
    int j = g_off[v], end = g_off[v + 1];
    float4 acc = make_float4(0.f, 0.f, 0.f, 0.f);

    for (; j + 8 <= end; j += 8) {
        int2 e[8];
#pragma unroll
        for (int q = 0; q < 8; q++) e[q] = __ldg(g_csr + j + q);
        float4 vv[8];
#pragma unroll
        for (int q = 0; q < 8; q++)
            vv[q] = *reinterpret_cast<const float4*>(x + (size_t)e[q].x * HD + lane * 4);
#pragma unroll
        for (int q = 0; q < 8; q++) {
            float w = __int_as_float(e[q].y);
            acc.x = fmaf(vv[q].x, w, acc.x);
            acc.y = fmaf(vv[q].y, w, acc.y);
            acc.z = fmaf(vv[q].z, w, acc.z);
            acc.w = fmaf(vv[q].w, w, acc.w);
        }
    }
    for (; j < end; j++) {
        int2 e = __ldg(g_csr + j);
        float w = __int_as_float(e.y);
        float4 vv = *reinterpret_cast<const float4*>(x + (size_t)e.x * HD + lane * 4);
        acc.x = fmaf(vv.x, w, acc.x); acc.y = fmaf(vv.y, w, acc.y);
        acc.z = fmaf(vv.z, w, acc.z); acc.w = fmaf(vv.w, w, acc.w);
    }
    // prefuse: A = x[v] + nc[v]*acc, split to bf16 hi/lo
    float ncv = __ldg(nc + v);
    float4 xv = *reinterpret_cast<const float4*>(x + (size_t)v * HD + lane * 4);
    float a0 = fmaf(acc.x, ncv, xv.x);
    float a1 = fmaf(acc.y, ncv, xv.y);
    float a2 = fmaf(acc.z, ncv, xv.z);
    float a3 = fmaf(acc.w, ncv, xv.w);
    uint2 hp, lp;
    split4(a0, a1, a2, a3, hp, lp);
    size_t bo = ((size_t)v * HD + lane * 4) * 2;
    *reinterpret_cast<uint2*>((char*)g_Ahi + bo) = hp;
    *reinterpret_cast<uint2*>((char*)g_Alo + bo) = lp;
}

// ---------------- fallback edge aggregation (atomic path, E > EMAX) ------------
__global__ __launch_bounds__(256, 4)
void edge_agg_kernel(const void* __restrict__ ei,
                     const float* __restrict__ ec,
                     int E, int sel, const float* __restrict__ xext) {
    __shared__ int s_src[EB];
    __shared__ int s_dst[EB];
    __shared__ float s_w[EB];
    int tid = threadIdx.x, wid = tid >> 5, lane = tid & 31;
    int is64 = g_idx64;
    const float* x = pick_x(sel, xext);

    long long base = (long long)blockIdx.x * EB;
    if (base >= E) return;
    int cnt = min(EB, (int)(E - base));
    if (tid < cnt) {
        s_src[tid] = (int)load_index(ei, base + tid, is64);
        s_dst[tid] = (int)load_index(ei, (long long)E + base + tid, is64);
        s_w[tid] = __ldg(ec + base + tid);
    }
    __syncthreads();

    int e = wid;
    if (e < cnt) {
        int s = s_src[e];
        float4 v = *reinterpret_cast<const float4*>(x + (size_t)s * HD + lane * 4);
        while (true) {
            int en = e + 8;
            float4 vn;
            if (en < cnt) {
                int sn = s_src[en];
                vn = *reinterpret_cast<const float4*>(x + (size_t)sn * HD + lane * 4);
            }
            float w = s_w[e];
            int d = s_dst[e];
            float4 o = make_float4(v.x * w, v.y * w, v.z * w, v.w * w);
            red_add_v4(g_agg + (size_t)d * HD + lane * 4, o);
            if (en >= cnt) break;
            v = vn; e = en;
        }
    }
}

// ---------------- tensor-core bf16x3 fused GEMM (persistent, 64-row tiles) -----
// 2 CTAs/SM. MODE 0: A prefused (g_Ahi/g_Alo), C = h1, accumulate col stats.
// MODE 1: BN(scale/shift computed per-CTA from g_stats)+relu on h1, C = relu(.@W2+b2).
// MODE 2: legacy fused A = x + agg*nc (fallback path), stats like MODE 0.
#define TM 64                                // tile rows
#define TILE_A_BYTES (TM * BPAD * 2)         // 17408
#define TILE_B_BYTES (HD * BPAD * 2)         // 34816
#define S_AHI 0
#define S_ALO TILE_A_BYTES
#define S_BHI (2 * TILE_A_BYTES)
#define S_BLO (2 * TILE_A_BYTES + TILE_B_BYTES)
#define SMEM_SZ (2 * TILE_A_BYTES + 2 * TILE_B_BYTES)   // 104448

template <int MODE>
__global__ __launch_bounds__(256, 2)
void tgemm_kernel(const float* __restrict__ nc,
                  const float* __restrict__ gamma,
                  const float* __restrict__ beta,
                  const float* __restrict__ bias,
                  int n, int sel, int slot,
                  const float* __restrict__ xext) {
    extern __shared__ char smem[];
    __shared__ __align__(16) float s_scale[HD];
    __shared__ __align__(16) float s_shift[HD];
    uint32_t sb = smem_u32(smem);
    int tid = threadIdx.x, wid = tid >> 5, lane = tid & 31;
    int warp_m = wid & 1;                    // rows warp_m*32
    int warp_n = wid >> 1;                   // cols warp_n*32

    const float* Ain = nullptr;
    float* Cout;
    if (MODE == 1) { Ain = g_h1; Cout = sel ? g_xB : g_xA; }
    else if (MODE == 2) { Ain = pick_x(sel, xext); Cout = g_h1; }
    else { Cout = g_h1; }

    // MODE 1: compute BN scale/shift per-CTA from global stats (cheap, redundant)
    if (MODE == 1) {
        if (tid < HD) {
            float invn = 1.f / (float)n;
            float mu = g_stats[tid] * invn;
            float var = g_stats[HD + tid] * invn - mu * mu;
            float s = gamma[tid] * rsqrtf(var + 1e-5f);
            s_scale[tid] = s;
            s_shift[tid] = beta[tid] - mu * s;
        }
        __syncthreads();
    }

    // ---- copy pre-split W tiles ONCE per CTA (already padded image) ----
    {
        const uint4* wh = (const uint4*)g_Whi[slot];
        const uint4* wl = (const uint4*)g_Wlo[slot];
        uint4* dh = (uint4*)(smem + S_BHI);
        uint4* dl = (uint4*)(smem + S_BLO);
        for (int i = tid; i < TILE_B_BYTES / 16; i += 256) {
            dh[i] = wh[i];
            dl[i] = wl[i];
        }
    }

    // per-lane ldmatrix base offsets
    int lrow = lane & 15;
    int lblk = (lane >> 4) * 16;
    uint32_t aBase = sb + (warp_m * 32 + lrow) * (BPAD * 2) + lblk;
    uint32_t bBase = sb + lrow * (BPAD * 2) + (warp_n * 32) * 2 + lblk;

    int tiles = (n + TM - 1) / TM;
    for (int t = blockIdx.x; t < tiles; t += gridDim.x) {
        int block_row = t * TM;

        // ---- A producer ----
#pragma unroll 4
        for (int it = 0; it < 8; it++) {
            int f = tid + it * 256;              // 0..2047 float4 slots
            int row = f >> 5;                    // 0..63
            int kk = (f & 31) << 2;              // 0..124
            int grow = block_row + row;
            int off = row * (BPAD * 2) + kk * 2;     // bytes
            if (MODE == 0) {
                // prefused: plain bf16 copy from g_Ahi/g_Alo
                uint2 hp = make_uint2(0u, 0u), lp = make_uint2(0u, 0u);
                if (grow < n) {
                    size_t bo = ((size_t)grow * HD + kk) * 2;
                    hp = *reinterpret_cast<const uint2*>((const char*)g_Ahi + bo);
                    lp = *reinterpret_cast<const uint2*>((const char*)g_Alo + bo);
                }
                *(uint2*)(smem + S_AHI + off) = hp;
                *(uint2*)(smem + S_ALO + off) = lp;
            } else {
                float4 v = make_float4(0.f, 0.f, 0.f, 0.f);
                if (grow < n) {
                    v = *reinterpret_cast<const float4*>(Ain + (size_t)grow * HD + kk);
                    if (MODE == 2) {
                        float w = __ldg(nc + grow);
                        float4 u = *reinterpret_cast<const float4*>(g_agg + (size_t)grow * HD + kk);
                        v.x = fmaf(u.x, w, v.x);
                        v.y = fmaf(u.y, w, v.y);
                        v.z = fmaf(u.z, w, v.z);
                        v.w = fmaf(u.w, w, v.w);
                    } else {
                        float4 sc = *reinterpret_cast<const float4*>(s_scale + kk);
                        float4 sh = *reinterpret_cast<const float4*>(s_shift + kk);
                        v.x = fmaxf(fmaf(v.x, sc.x, sh.x), 0.f);
                        v.y = fmaxf(fmaf(v.y, sc.y, sh.y), 0.f);
                        v.z = fmaxf(fmaf(v.z, sc.z, sh.z), 0.f);
                        v.w = fmaxf(fmaf(v.w, sc.w, sh.w), 0.f);
                    }
                }
                uint2 hp, lp;
                split4(v.x, v.y, v.z, v.w, hp, lp);
                *(uint2*)(smem + S_AHI + off) = hp;
                *(uint2*)(smem + S_ALO + off) = lp;
            }
        }
        __syncthreads();

        // ---- MMA mainloop: 8 k-steps, 3 products, fp32 accumulate ----
        float acc[2][4][4];
#pragma unroll
        for (int mf = 0; mf < 2; mf++)
#pragma unroll
            for (int nf = 0; nf < 4; nf++)
#pragma unroll
                for (int q = 0; q < 4; q++) acc[mf][nf][q] = 0.f;

#pragma unroll
        for (int ks = 0; ks < 8; ks++) {
            uint32_t ah[2][4], al[2][4], bh[4][2], bl[4][2];
#pragma unroll
            for (int mf = 0; mf < 2; mf++) {
                uint32_t addr = aBase + mf * 16 * (BPAD * 2) + ks * 32;
                ldmatrix_x4(ah[mf], addr + S_AHI);
                ldmatrix_x4(al[mf], addr + S_ALO);
            }
#pragma unroll
            for (int nb = 0; nb < 2; nb++) {
                uint32_t addr = bBase + ks * 16 * (BPAD * 2) + nb * 32;
                uint32_t rh[4], rl[4];
                ldmatrix_x4_trans(rh, addr + S_BHI);
                ldmatrix_x4_trans(rl, addr + S_BLO);
                bh[2 * nb][0] = rh[0]; bh[2 * nb][1] = rh[1];
                bh[2 * nb + 1][0] = rh[2]; bh[2 * nb + 1][1] = rh[3];
                bl[2 * nb][0] = rl[0]; bl[2 * nb][1] = rl[1];
                bl[2 * nb + 1][0] = rl[2]; bl[2 * nb + 1][1] = rl[3];
            }
#pragma unroll
            for (int mf = 0; mf < 2; mf++)
#pragma unroll
                for (int nf = 0; nf < 4; nf++) {
                    mma_bf16(acc[mf][nf], ah[mf], bh[nf]);
                    mma_bf16(acc[mf][nf], ah[mf], bl[nf]);
                    mma_bf16(acc[mf][nf], al[mf], bh[nf]);
                }
        }

        // ---- epilogue: bias, (stats | relu), direct fragment stores ----
        int r0 = block_row + warp_m * 32 + (lane >> 2);
#pragma unroll
        for (int nf = 0; nf < 4; nf++) {
            int col = warp_n * 32 + nf * 8 + (lane & 3) * 2;
            float b0 = __ldg(bias + col), b1 = __ldg(bias + col + 1);
            float v[4][2];
#pragma unroll
            for (int mf = 0; mf < 2; mf++) {
                v[mf * 2][0] = acc[mf][nf][0] + b0;
                v[mf * 2][1] = acc[mf][nf][1] + b1;
                v[mf * 2 + 1][0] = acc[mf][nf][2] + b0;
                v[mf * 2 + 1][1] = acc[mf][nf][3] + b1;
            }
            bool val[4];
            val[0] = r0 < n; val[1] = r0 + 8 < n; val[2] = r0 + 16 < n; val[3] = r0 + 24 < n;
            if (MODE != 1) {
                float s0 = 0.f, s1 = 0.f, q0 = 0.f, q1 = 0.f;
#pragma unroll
                for (int p = 0; p < 4; p++) {
                    if (val[p]) {
                        s0 += v[p][0]; q0 += v[p][0] * v[p][0];
                        s1 += v[p][1]; q1 += v[p][1] * v[p][1];
                    }
                }
#pragma unroll
                for (int d = 4; d < 32; d <<= 1) {
                    s0 += __shfl_xor_sync(0xFFFFFFFFu, s0, d);
                    s1 += __shfl_xor_sync(0xFFFFFFFFu, s1, d);
                    q0 += __shfl_xor_sync(0xFFFFFFFFu, q0, d);
                    q1 += __shfl_xor_sync(0xFFFFFFFFu, q1, d);
                }
                if (lane < 4) {
                    int c0 = warp_n * 32 + nf * 8 + lane * 2;
                    atomicAdd(&g_stats[c0], s0);
                    atomicAdd(&g_stats[c0 + 1], s1);
                    atomicAdd(&g_stats[HD + c0], q0);
                    atomicAdd(&g_stats[HD + c0 + 1], q1);
                }
            } else {
#pragma unroll
                for (int p = 0; p < 4; p++) {
                    v[p][0] = fmaxf(v[p][0], 0.f);
                    v[p][1] = fmaxf(v[p][1], 0.f);
                }
            }
#pragma unroll
            for (int p = 0; p < 4; p++) {
                int row = r0 + ((p & 1) ? 8 : 0) + ((p >> 1) ? 16 : 0);
                int pi = (p & 1) + (p >> 1) * 2;
                if (row < n) {
                    float2 o = make_float2(v[pi][0], v[pi][1]);
                    *reinterpret_cast<float2*>(Cout + (size_t)row * HD + col) = o;
                }
            }
        }
        __syncthreads();   // A SMEM reuse barrier before next tile's producer
    }
}

// ---------------- segmented pooling (batch is sorted) ---------------------------
__global__ void pool_kernel(const void* __restrict__ batch, int n, int sel) {
    int w = blockIdx.x * (blockDim.x >> 5) + (threadIdx.x >> 5);
    int base = w * 32;
    if (base >= n) return;
    int lane = threadIdx.x & 31;
    int is64 = g_idx64;
    const float* x = sel ? g_xB : g_xA;
    int end = min(base + 32, n);

    float4 acc = make_float4(0.f, 0.f, 0.f, 0.f);
    float cnt = 0.f;
    int cur = (int)load_index(batch, base, is64);
    for (int i = base; i < end; i++) {
        int g = (int)load_index(batch, i, is64);
        if (g != cur) {
            red_add_v4(g_pool + (size_t)cur * HD + lane * 4, acc);
            if (lane == 0) atomicAdd(&g_cnt[cur], cnt);
            acc = make_float4(0.f, 0.f, 0.f, 0.f);
            cnt = 0.f;
            cur = g;
        }
        float4 v = *reinterpret_cast<const float4*>(x + (size_t)i * HD + lane * 4);
        acc.x += v.x; acc.y += v.y; acc.z += v.z; acc.w += v.w;
        cnt += 1.f;
    }
    red_add_v4(g_pool + (size_t)cur * HD + lane * 4, acc);
    if (lane == 0) atomicAdd(&g_cnt[cur], cnt);
}

// ---------------- classifier head ----------------------------------------------
__global__ void head_kernel(const float* __restrict__ Wc,
                            const float* __restrict__ bc,
                            float* __restrict__ out) {
    int g = blockIdx.x;
    int h = threadIdx.x;
    float cnt = g_cnt[g];
    float v = g_pool[g * HD + h] / fmaxf(cnt, 1.f);
    __shared__ float sh[HD];
    for (int c = 0; c < NCLS; c++) {
        sh[h] = v * Wc[h * NCLS + c];
        __syncthreads();
        for (int s = 64; s > 0; s >>= 1) {
            if (h < s) sh[h] += sh[h + s];
            __syncthreads();
        }
        if (h == 0) out[g * NCLS + c] = sh[0] + bc[c];
        __syncthreads();
    }
}

// ---------------- launch ---------------------------------------------------------
extern "C" void kernel_launch(void* const* d_in, const int* in_sizes, int n_in,
                              void* d_out, int out_size) {
    cudaFuncSetAttribute(tgemm_kernel<0>,
                         cudaFuncAttributeMaxDynamicSharedMemorySize, SMEM_SZ);
    cudaFuncSetAttribute(tgemm_kernel<1>,
                         cudaFuncAttributeMaxDynamicSharedMemorySize, SMEM_SZ);
    cudaFuncSetAttribute(tgemm_kernel<2>,
                         cudaFuncAttributeMaxDynamicSharedMemorySize, SMEM_SZ);

    // Detect input ordering: signature order has edge_index (1.6M elems) at [1];
    // setup_inputs dict order has node_centrality (50K) at [1].
    int ix, iei, ib, inc_, iec, iw1, ib1, ig1, ibe1, iw2, ib2, iwc, ibc;
    ix = 0;
    if (n_in >= 13 && in_sizes[1] > 1000000) {
        iei = 1; ib = 2; inc_ = 3; iec = 4;
        iw1 = 5; ib1 = 6; ig1 = 7; ibe1 = 8;
        iw2 = 9; ib2 = 10; iwc = 11; ibc = 12;
    } else {
        inc_ = 1; iec = 2; iw1 = 3; ib1 = 4; ig1 = 5; ibe1 = 6;
        iw2 = 7; ib2 = 8; iwc = 9; ibc = 10; iei = 11; ib = 12;
    }

    const float* x   = (const float*)d_in[ix];
    const void*  ei  = d_in[iei];
    const void*  bat = d_in[ib];
    const float* nc  = (const float*)d_in[inc_];
    const float* ec  = (const float*)d_in[iec];
    const float* W1  = (const float*)d_in[iw1];
    const float* b1  = (const float*)d_in[ib1];
    const float* g1  = (const float*)d_in[ig1];
    const float* be1 = (const float*)d_in[ibe1];
    const float* W2  = (const float*)d_in[iw2];
    const float* b2  = (const float*)d_in[ib2];
    const float* Wc  = (const float*)d_in[iwc];
    const float* bc  = (const float*)d_in[ibc];
    float* out = (float*)d_out;

    int n = in_sizes[ix] / HD;
    int E = in_sizes[iei] / 2;
    int n4 = n * (HD / 4);
    bool use_csr = (E <= EMAX) && (n <= NMAX);

    // conv_w + idx-detect + deg-zero in one launch
    int cw_threads = 6 * HD * HD > n + 1 ? 6 * HD * HD : n + 1;
    conv_w_all_kernel<<<(cw_threads + 255) / 256, 256>>>(W1, W2, ei, E, n);
    zero_stats_pool_kernel<<<(NG * HD + 255) / 256, 256>>>(n);

    int tiles = (n + TM - 1) / TM;
    int gemm_grid = tiles < 296 ? tiles : 296;
    int pool_blocks = (n + 255) / 256;   // 8 warps x 32 nodes per block

    if (use_csr) {
        int nchunks = (n + 511) / 512;
        hist_kernel<<<512, 256>>>(ei, E);
        scan1_kernel<<<nchunks, 512>>>(n);
        scan2_kernel<<<1, 512>>>(nchunks, E, n);
        scan3_kernel<<<(n + 255) / 256, 256>>>(n);
        scatter_kernel<<<512, 256>>>(ei, ec, E);
    }

    int agg_blocks = (n + 7) / 8;
    int edge_blocks = (E + EB - 1) / EB;

    // layer I/O: in x(ext) -> B -> A -> B  (sel<0 means external x)
    int sel_in_tab[3]  = { -1, 1, 0 };
    int sel_out_tab[3] = { 1, 0, 1 };

    for (int l = 0; l < 3; l++) {
        int sel_in = sel_in_tab[l];
        int sel_out = sel_out_tab[l];
        if (use_csr) {
            csr_agg_kernel<<<agg_blocks, 256>>>(n, sel_in, x, nc);
            tgemm_kernel<0><<<gemm_grid, 256, SMEM_SZ>>>(
                nullptr, nullptr, nullptr, b1 + l * HD, n, 0, l, x);
        } else {
            zero_agg_stats_kernel<<<2048, 256>>>(n4);
            edge_agg_kernel<<<edge_blocks, 256>>>(ei, ec, E, sel_in, x);
            tgemm_kernel<2><<<gemm_grid, 256, SMEM_SZ>>>(
                nc, nullptr, nullptr, b1 + l * HD, n, sel_in, l, x);
        }
        tgemm_kernel<1><<<gemm_grid, 256, SMEM_SZ>>>(
            nullptr, g1 + l * HD, be1 + l * HD, b2 + l * HD, n, sel_out, 3 + l, x);
    }

    pool_kernel<<<pool_blocks, 256>>>(bat, n, 1);  // final activations live in g_xB
    head_kernel<<<NG, HD>>>(Wc, bc, out);
}

// round 12
// speedup vs baseline: 1.0067x; 1.0067x over previous
#include <cuda_runtime.h>
#include <cuda_bf16.h>
#include <cstdint>

#define NMAX 50000
#define EMAX 800000
#define HD 128
#define NG 128
#define NCLS 10
#define BPAD 136                      // padded row stride (bf16 elems), 272B: conflict-free ldmatrix
#define EB 128                        // edges staged per block (fallback path)

// ---------------- scratch (device globals; no runtime allocation) -----------
// NOTE: referenced ONLY from device code (selected via int selectors).
// Host-passed &g_x* resolves to host shadow memory (NVLink-C2C, 15-22x slow).
// Harness pointers (d_in[i]) are true device pointers and safe as kernel args.
__device__ float g_xA[NMAX * HD];
__device__ float g_xB[NMAX * HD];
__device__ float g_agg[NMAX * HD];   // fallback (atomic) path only
__device__ float g_h1[NMAX * HD];
__device__ __nv_bfloat16 g_Ahi[NMAX * HD];   // prefused A = x + nc*agg, hi part
__device__ __nv_bfloat16 g_Alo[NMAX * HD];   // lo part (error compensation)
__device__ float g_stats[2 * HD];   // [0:128) col sums, [128:256) col sumsq
__device__ float g_pool[NG * HD];
__device__ float g_cnt[NG];
__device__ int   g_idx64;           // 1 if indices are int64, 0 if int32
// CSR of the (static) edge set, built once per call; (src, w) packed as int2
__device__ int   g_deg[NMAX + 1];
__device__ int   g_off[NMAX + 1];
__device__ int   g_cursor[NMAX];
__device__ int   g_csum[128];       // per-chunk totals (lookback scan)
__device__ int   g_flag[128];       // publish flags (lookback scan)
__device__ int2  g_csr[EMAX];
// pre-split weights in the padded SMEM image: [k][n], row stride BPAD
__device__ __nv_bfloat16 g_Whi[6][HD * BPAD];
__device__ __nv_bfloat16 g_Wlo[6][HD * BPAD];

// ---------------- helpers -----------------------------------------------------
__device__ __forceinline__ uint32_t smem_u32(const void* p) {
    uint32_t a;
    asm("{ .reg .u64 t; cvta.to.shared.u64 t, %1; cvt.u32.u64 %0, t; }"
        : "=r"(a) : "l"(p));
    return a;
}
__device__ __forceinline__ void red_add_v4(float* p, float4 v) {
    asm volatile("red.global.add.v4.f32 [%0], {%1,%2,%3,%4};"
                 :: "l"(p), "f"(v.x), "f"(v.y), "f"(v.z), "f"(v.w)
                 : "memory");
}
__device__ __forceinline__ void cp_async16(uint32_t dst, const void* src) {
    asm volatile("cp.async.ca.shared.global [%0], [%1], 16;"
                 :: "r"(dst), "l"(src) : "memory");
}
__device__ __forceinline__ void cp_async16_zero(uint32_t dst, const void* src) {
    asm volatile("cp.async.ca.shared.global [%0], [%1], 16, 0;"
                 :: "r"(dst), "l"(src) : "memory");
}
__device__ __forceinline__ uint32_t pack_bf(__nv_bfloat16 a, __nv_bfloat16 b) {
    uint16_t ua = *(uint16_t*)&a, ub = *(uint16_t*)&b;
    return (uint32_t)ua | ((uint32_t)ub << 16);
}
__device__ __forceinline__ void split4(float a0, float a1, float a2, float a3,
                                       uint2& hp, uint2& lp) {
    __nv_bfloat16 h0 = __float2bfloat16(a0);
    __nv_bfloat16 h1 = __float2bfloat16(a1);
    __nv_bfloat16 h2 = __float2bfloat16(a2);
    __nv_bfloat16 h3 = __float2bfloat16(a3);
    __nv_bfloat16 l0 = __float2bfloat16(a0 - __bfloat162float(h0));
    __nv_bfloat16 l1 = __float2bfloat16(a1 - __bfloat162float(h1));
    __nv_bfloat16 l2 = __float2bfloat16(a2 - __bfloat162float(h2));
    __nv_bfloat16 l3 = __float2bfloat16(a3 - __bfloat162float(h3));
    hp.x = pack_bf(h0, h1); hp.y = pack_bf(h2, h3);
    lp.x = pack_bf(l0, l1); lp.y = pack_bf(l2, l3);
}
__device__ __forceinline__ void ldmatrix_x4(uint32_t* r, uint32_t addr) {
    asm volatile("ldmatrix.sync.aligned.m8n8.x4.shared.b16 {%0,%1,%2,%3}, [%4];"
                 : "=r"(r[0]), "=r"(r[1]), "=r"(r[2]), "=r"(r[3]) : "r"(addr));
}
__device__ __forceinline__ void ldmatrix_x4_trans(uint32_t* r, uint32_t addr) {
    asm volatile("ldmatrix.sync.aligned.m8n8.x4.trans.shared.b16 {%0,%1,%2,%3}, [%4];"
                 : "=r"(r[0]), "=r"(r[1]), "=r"(r[2]), "=r"(r[3]) : "r"(addr));
}
__device__ __forceinline__ void mma_bf16(float* c, const uint32_t* a, const uint32_t* b) {
    asm volatile(
        "mma.sync.aligned.m16n8k16.row.col.f32.bf16.bf16.f32 "
        "{%0,%1,%2,%3}, {%4,%5,%6,%7}, {%8,%9}, {%0,%1,%2,%3};"
        : "+f"(c[0]), "+f"(c[1]), "+f"(c[2]), "+f"(c[3])
        : "r"(a[0]), "r"(a[1]), "r"(a[2]), "r"(a[3]), "r"(b[0]), "r"(b[1]));
}
__device__ __forceinline__ long long load_index(const void* base, long long off, int is64) {
    if (is64) return ((const long long*)base)[off];
    return (long long)((const int*)base)[off];
}
// layer input select: sel<0 -> external harness pointer, 0 -> g_xA, 1 -> g_xB
__device__ __forceinline__ const float* pick_x(int sel, const float* xext) {
    if (sel < 0) return xext;
    return sel ? g_xB : g_xA;
}

// ---------------- fallback zeroing (atomic path only) --------------------------
__global__ void zero_agg_stats_kernel(int n4) {
    int i = blockIdx.x * blockDim.x + threadIdx.x;
    if (i < 2 * HD) g_stats[i] = 0.f;
    float4 z = make_float4(0.f, 0.f, 0.f, 0.f);
    float4* a = reinterpret_cast<float4*>(g_agg);
    for (int j = i; j < n4; j += gridDim.x * blockDim.x) a[j] = z;
}

// ------- weight pre-split + idx detect + deg/pool/flag zero (one launch) -------
__global__ void conv_w_all_kernel(const float* __restrict__ W1,
                                  const float* __restrict__ W2,
                                  const void* __restrict__ ei, int E, int n_nodes) {
    int i = blockIdx.x * blockDim.x + threadIdx.x;
    if (i == 0) {           // fold index-dtype detection into this launch
        const long long* p64 = (const long long*)ei;
        int ok64 = 1;
        for (int t = 0; t < 16; t++) {
            long long v = p64[t];
            if (v < 0 || v >= (long long)n_nodes) { ok64 = 0; break; }
        }
        if (ok64) {
            for (int t = 0; t < 16; t++) {
                long long v = p64[(size_t)E + t];
                if (v < 0 || v >= (long long)n_nodes) { ok64 = 0; break; }
            }
        }
        g_idx64 = ok64;
    }
    if (i <= n_nodes) g_deg[i] = 0;      // degree-array zeroing
    if (i < NG * HD) g_pool[i] = 0.f;    // pool zeroing
    if (i < NG) g_cnt[i] = 0.f;
    if (i < 128) g_flag[i] = 0;          // lookback-scan flags
    if (i >= 6 * HD * HD) return;
    int slot = i >> 14;
    int j = i & (HD * HD - 1);
    int n = j & 127, k = j >> 7;
    const float* W = (slot < 3) ? (W1 + (size_t)slot * HD * HD)
                                : (W2 + (size_t)(slot - 3) * HD * HD);
    float w = W[k * HD + n];
    __nv_bfloat16 hi = __float2bfloat16(w);
    float lof = w - __bfloat162float(hi);
    g_Whi[slot][k * BPAD + n] = hi;
    g_Wlo[slot][k * BPAD + n] = __float2bfloat16(lof);
}

// ---------------- CSR construction (once per call) -----------------------------
__global__ void hist_kernel(const void* __restrict__ ei, int E) {
    int is64 = g_idx64;
    for (long long e = blockIdx.x * blockDim.x + threadIdx.x; e < E;
         e += (long long)gridDim.x * blockDim.x) {
        int d = (int)load_index(ei, (long long)E + e, is64);
        atomicAdd(&g_deg[d], 1);
    }
}
// Fused exclusive scan over g_deg via decoupled lookback. Grid = nchunks (<=128)
// blocks of 512; each publishes its chunk total, then sums all lower chunks.
// Deadlock-free: dependencies point strictly downward and nchunks < #SMs.
__global__ void scan_fused_kernel(int n, int E, int nchunks) {
    __shared__ int sh[512];
    __shared__ int s_prefix;
    int t = threadIdx.x;
    int chunk = blockIdx.x;
    int i = chunk * 512 + t;
    int v = (i < n) ? g_deg[i] : 0;
    sh[t] = v;
    __syncthreads();
#pragma unroll
    for (int o = 1; o < 512; o <<= 1) {
        int tmp = (t >= o) ? sh[t - o] : 0;
        __syncthreads();
        sh[t] += tmp;
        __syncthreads();
    }
    if (t == 0) {
        g_csum[chunk] = sh[511];
        __threadfence();
        atomicExch(&g_flag[chunk], 1);
        s_prefix = 0;
    }
    __syncthreads();
    if (t < 32) {
        int p = 0;
        for (int c = t; c < chunk; c += 32) {
            while (atomicAdd(&g_flag[c], 0) == 0) { }
            __threadfence();
            p += g_csum[c];
        }
#pragma unroll
        for (int d = 16; d; d >>= 1) p += __shfl_xor_sync(0xFFFFFFFFu, p, d);
        if (t == 0) s_prefix = p;
    }
    __syncthreads();
    if (i < n) {
        int o = sh[t] - v + s_prefix;    // exclusive global offset
        g_off[i] = o;
        g_cursor[i] = o;
    }
    if (chunk == nchunks - 1 && t == 0) g_off[n] = E;
}
__global__ void scatter_kernel(const void* __restrict__ ei,
                               const float* __restrict__ ec, int E) {
    int is64 = g_idx64;
    for (long long e = blockIdx.x * blockDim.x + threadIdx.x; e < E;
         e += (long long)gridDim.x * blockDim.x) {
        int s = (int)load_index(ei, e, is64);
        int d = (int)load_index(ei, (long long)E + e, is64);
        float w = __ldg(ec + e);
        int pos = atomicAdd(&g_cursor[d], 1);
        g_csr[pos] = make_int2(s, __float_as_int(w));
    }
}

// ---------------- CSR aggregation + A prefusion --------------------------------
// Warp per node; 8-wide batched gathers; fuses A = x + nc*agg, splits bf16
// hi/lo, writes g_Ahi/g_Alo directly. Block 0 also resets g_stats for the
// coming tgemm<0> (previous tgemm<1> consumers already finished, stream order).
__global__ __launch_bounds__(256, 4)
void csr_agg_kernel(int n, int sel, const float* __restrict__ xext,
                    const float* __restrict__ nc) {
    if (blockIdx.x == 0 && threadIdx.x < 2 * HD) g_stats[threadIdx.x] = 0.f;
    int v = blockIdx.x * 8 + (threadIdx.x >> 5);
    if (v >= n) return;
    int lane = threadIdx.x & 31;
    const float* x = pick_x(sel, xext);
    int j = g_off[v], end = g_off[v + 1];
    float4 acc = make_float4(0.f, 0.f, 0.f, 0.f);

    for (; j + 8 <= end; j += 8) {
        int2 e[8];
#pragma unroll
        for (int q = 0; q < 8; q++) e[q] = __ldg(g_csr + j + q);
        float4 vv[8];
#pragma unroll
        for (int q = 0; q < 8; q++)
            vv[q] = *reinterpret_cast<const float4*>(x + (size_t)e[q].x * HD + lane * 4);
#pragma unroll
        for (int q = 0; q < 8; q++) {
            float w = __int_as_float(e[q].y);
            acc.x = fmaf(vv[q].x, w, acc.x);
            acc.y = fmaf(vv[q].y, w, acc.y);
            acc.z = fmaf(vv[q].z, w, acc.z);
            acc.w = fmaf(vv[q].w, w, acc.w);
        }
    }
    for (; j < end; j++) {
        int2 e = __ldg(g_csr + j);
        float w = __int_as_float(e.y);
        float4 vv = *reinterpret_cast<const float4*>(x + (size_t)e.x * HD + lane * 4);
        acc.x = fmaf(vv.x, w, acc.x); acc.y = fmaf(vv.y, w, acc.y);
        acc.z = fmaf(vv.z, w, acc.z); acc.w = fmaf(vv.w, w, acc.w);
    }
    // prefuse: A = x[v] + nc[v]*acc, split to bf16 hi/lo
    float ncv = __ldg(nc + v);
    float4 xv = *reinterpret_cast<const float4*>(x + (size_t)v * HD + lane * 4);
    float a0 = fmaf(acc.x, ncv, xv.x);
    float a1 = fmaf(acc.y, ncv, xv.y);
    float a2 = fmaf(acc.z, ncv, xv.z);
    float a3 = fmaf(acc.w, ncv, xv.w);
    uint2 hp, lp;
    split4(a0, a1, a2, a3, hp, lp);
    size_t bo = ((size_t)v * HD + lane * 4) * 2;
    *reinterpret_cast<uint2*>((char*)g_Ahi + bo) = hp;
    *reinterpret_cast<uint2*>((char*)g_Alo + bo) = lp;
}

// ---------------- fallback edge aggregation (atomic path, E > EMAX) ------------
__global__ __launch_bounds__(256, 4)
void edge_agg_kernel(const void* __restrict__ ei,
                     const float* __restrict__ ec,
                     int E, int sel, const float* __restrict__ xext) {
    __shared__ int s_src[EB];
    __shared__ int s_dst[EB];
    __shared__ float s_w[EB];
    int tid = threadIdx.x, wid = tid >> 5, lane = tid & 31;
    int is64 = g_idx64;
    const float* x = pick_x(sel, xext);

    long long base = (long long)blockIdx.x * EB;
    if (base >= E) return;
    int cnt = min(EB, (int)(E - base));
    if (tid < cnt) {
        s_src[tid] = (int)load_index(ei, base + tid, is64);
        s_dst[tid] = (int)load_index(ei, (long long)E + base + tid, is64);
        s_w[tid] = __ldg(ec + base + tid);
    }
    __syncthreads();

    int e = wid;
    if (e < cnt) {
        int s = s_src[e];
        float4 v = *reinterpret_cast<const float4*>(x + (size_t)s * HD + lane * 4);
        while (true) {
            int en = e + 8;
            float4 vn;
            if (en < cnt) {
                int sn = s_src[en];
                vn = *reinterpret_cast<const float4*>(x + (size_t)sn * HD + lane * 4);
            }
            float w = s_w[e];
            int d = s_dst[e];
            float4 o = make_float4(v.x * w, v.y * w, v.z * w, v.w * w);
            red_add_v4(g_agg + (size_t)d * HD + lane * 4, o);
            if (en >= cnt) break;
            v = vn; e = en;
        }
    }
}

// ---------------- tensor-core bf16x3 fused GEMM (persistent, 64-row tiles) -----
// 2 CTAs/SM. MODE 0: A prefused (g_Ahi/g_Alo), cp.async copy producer, C = h1,
//                    accumulate col stats.
// MODE 1: BN(scale/shift computed per-CTA from g_stats)+relu on h1, C = relu(.@W2+b2).
// MODE 2: legacy fused A = x + agg*nc (fallback path), stats like MODE 0.
#define TM 64                                // tile rows
#define TILE_A_BYTES (TM * BPAD * 2)         // 17408
#define TILE_B_BYTES (HD * BPAD * 2)         // 34816
#define S_AHI 0
#define S_ALO TILE_A_BYTES
#define S_BHI (2 * TILE_A_BYTES)
#define S_BLO (2 * TILE_A_BYTES + TILE_B_BYTES)
#define SMEM_SZ (2 * TILE_A_BYTES + 2 * TILE_B_BYTES)   // 104448

template <int MODE>
__global__ __launch_bounds__(256, 2)
void tgemm_kernel(const float* __restrict__ nc,
                  const float* __restrict__ gamma,
                  const float* __restrict__ beta,
                  const float* __restrict__ bias,
                  int n, int sel, int slot,
                  const float* __restrict__ xext) {
    extern __shared__ char smem[];
    __shared__ __align__(16) float s_scale[HD];
    __shared__ __align__(16) float s_shift[HD];
    uint32_t sb = smem_u32(smem);
    int tid = threadIdx.x, wid = tid >> 5, lane = tid & 31;
    int warp_m = wid & 1;                    // rows warp_m*32
    int warp_n = wid >> 1;                   // cols warp_n*32

    const float* Ain = nullptr;
    float* Cout;
    if (MODE == 1) { Ain = g_h1; Cout = sel ? g_xB : g_xA; }
    else if (MODE == 2) { Ain = pick_x(sel, xext); Cout = g_h1; }
    else { Cout = g_h1; }

    // MODE 1: compute BN scale/shift per-CTA from global stats (cheap, redundant)
    if (MODE == 1) {
        if (tid < HD) {
            float invn = 1.f / (float)n;
            float mu = g_stats[tid] * invn;
            float var = g_stats[HD + tid] * invn - mu * mu;
            float s = gamma[tid] * rsqrtf(var + 1e-5f);
            s_scale[tid] = s;
            s_shift[tid] = beta[tid] - mu * s;
        }
        __syncthreads();
    }

    // ---- copy pre-split W tiles ONCE per CTA (already padded image) ----
    {
        const uint4* wh = (const uint4*)g_Whi[slot];
        const uint4* wl = (const uint4*)g_Wlo[slot];
        uint4* dh = (uint4*)(smem + S_BHI);
        uint4* dl = (uint4*)(smem + S_BLO);
        for (int i = tid; i < TILE_B_BYTES / 16; i += 256) {
            dh[i] = wh[i];
            dl[i] = wl[i];
        }
    }

    // per-lane ldmatrix base offsets
    int lrow = lane & 15;
    int lblk = (lane >> 4) * 16;
    uint32_t aBase = sb + (warp_m * 32 + lrow) * (BPAD * 2) + lblk;
    uint32_t bBase = sb + lrow * (BPAD * 2) + (warp_n * 32) * 2 + lblk;

    int tiles = (n + TM - 1) / TM;
    for (int t = blockIdx.x; t < tiles; t += gridDim.x) {
        int block_row = t * TM;

        // ---- A producer ----
        if (MODE == 0) {
            // prefused: pure cp.async copy, 16B chunks (row = 256B = 16 chunks x2)
#pragma unroll
            for (int it = 0; it < 8; it++) {
                int f = tid + it * 256;          // 0..2047 chunk slots
                int row = f >> 5;                // 0..63
                int c = f & 31;                  // 0..31: c<16 hi, else lo
                int grow = block_row + row;
                bool hi = c < 16;
                int cc = hi ? c : c - 16;
                uint32_t dst = sb + (hi ? S_AHI : S_ALO) + row * (BPAD * 2) + cc * 16;
                if (grow < n) {
                    const char* srcp = (const char*)(hi ? g_Ahi : g_Alo)
                                     + ((size_t)grow * HD + cc * 8) * 2;
                    cp_async16(dst, srcp);
                } else {
                    cp_async16_zero(dst, (const void*)g_Ahi);
                }
            }
            asm volatile("cp.async.commit_group;" ::: "memory");
            asm volatile("cp.async.wait_group 0;" ::: "memory");
        } else {
#pragma unroll 4
            for (int it = 0; it < 8; it++) {
                int f = tid + it * 256;              // 0..2047 float4 slots
                int row = f >> 5;                    // 0..63
                int kk = (f & 31) << 2;              // 0..124
                int grow = block_row + row;
                int off = row * (BPAD * 2) + kk * 2;     // bytes
                float4 v = make_float4(0.f, 0.f, 0.f, 0.f);
                if (grow < n) {
                    v = *reinterpret_cast<const float4*>(Ain + (size_t)grow * HD + kk);
                    if (MODE == 2) {
                        float w = __ldg(nc + grow);
                        float4 u = *reinterpret_cast<const float4*>(g_agg + (size_t)grow * HD + kk);
                        v.x = fmaf(u.x, w, v.x);
                        v.y = fmaf(u.y, w, v.y);
                        v.z = fmaf(u.z, w, v.z);
                        v.w = fmaf(u.w, w, v.w);
                    } else {
                        float4 sc = *reinterpret_cast<const float4*>(s_scale + kk);
                        float4 sh = *reinterpret_cast<const float4*>(s_shift + kk);
                        v.x = fmaxf(fmaf(v.x, sc.x, sh.x), 0.f);
                        v.y = fmaxf(fmaf(v.y, sc.y, sh.y), 0.f);
                        v.z = fmaxf(fmaf(v.z, sc.z, sh.z), 0.f);
                        v.w = fmaxf(fmaf(v.w, sc.w, sh.w), 0.f);
                    }
                }
                uint2 hp, lp;
                split4(v.x, v.y, v.z, v.w, hp, lp);
                *(uint2*)(smem + S_AHI + off) = hp;
                *(uint2*)(smem + S_ALO + off) = lp;
            }
        }
        __syncthreads();

        // ---- MMA mainloop: 8 k-steps, 3 products, fp32 accumulate ----
        float acc[2][4][4];
#pragma unroll
        for (int mf = 0; mf < 2; mf++)
#pragma unroll
            for (int nf = 0; nf < 4; nf++)
#pragma unroll
                for (int q = 0; q < 4; q++) acc[mf][nf][q] = 0.f;

#pragma unroll
        for (int ks = 0; ks < 8; ks++) {
            uint32_t ah[2][4], al[2][4], bh[4][2], bl[4][2];
#pragma unroll
            for (int mf = 0; mf < 2; mf++) {
                uint32_t addr = aBase + mf * 16 * (BPAD * 2) + ks * 32;
                ldmatrix_x4(ah[mf], addr + S_AHI);
                ldmatrix_x4(al[mf], addr + S_ALO);
            }
#pragma unroll
            for (int nb = 0; nb < 2; nb++) {
                uint32_t addr = bBase + ks * 16 * (BPAD * 2) + nb * 32;
                uint32_t rh[4], rl[4];
                ldmatrix_x4_trans(rh, addr + S_BHI);
                ldmatrix_x4_trans(rl, addr + S_BLO);
                bh[2 * nb][0] = rh[0]; bh[2 * nb][1] = rh[1];
                bh[2 * nb + 1][0] = rh[2]; bh[2 * nb + 1][1] = rh[3];
                bl[2 * nb][0] = rl[0]; bl[2 * nb][1] = rl[1];
                bl[2 * nb + 1][0] = rl[2]; bl[2 * nb + 1][1] = rl[3];
            }
#pragma unroll
            for (int mf = 0; mf < 2; mf++)
#pragma unroll
                for (int nf = 0; nf < 4; nf++) {
                    mma_bf16(acc[mf][nf], ah[mf], bh[nf]);
                    mma_bf16(acc[mf][nf], ah[mf], bl[nf]);
                    mma_bf16(acc[mf][nf], al[mf], bh[nf]);
                }
        }

        // ---- epilogue: bias, (stats | relu), direct fragment stores ----
        int r0 = block_row + warp_m * 32 + (lane >> 2);
#pragma unroll
        for (int nf = 0; nf < 4; nf++) {
            int col = warp_n * 32 + nf * 8 + (lane & 3) * 2;
            float b0 = __ldg(bias + col), b1 = __ldg(bias + col + 1);
            float v[4][2];
#pragma unroll
            for (int mf = 0; mf < 2; mf++) {
                v[mf * 2][0] = acc[mf][nf][0] + b0;
                v[mf * 2][1] = acc[mf][nf][1] + b1;
                v[mf * 2 + 1][0] = acc[mf][nf][2] + b0;
                v[mf * 2 + 1][1] = acc[mf][nf][3] + b1;
            }
            bool val[4];
            val[0] = r0 < n; val[1] = r0 + 8 < n; val[2] = r0 + 16 < n; val[3] = r0 + 24 < n;
            if (MODE != 1) {
                float s0 = 0.f, s1 = 0.f, q0 = 0.f, q1 = 0.f;
#pragma unroll
                for (int p = 0; p < 4; p++) {
                    if (val[p]) {
                        s0 += v[p][0]; q0 += v[p][0] * v[p][0];
                        s1 += v[p][1]; q1 += v[p][1] * v[p][1];
                    }
                }
#pragma unroll
                for (int d = 4; d < 32; d <<= 1) {
                    s0 += __shfl_xor_sync(0xFFFFFFFFu, s0, d);
                    s1 += __shfl_xor_sync(0xFFFFFFFFu, s1, d);
                    q0 += __shfl_xor_sync(0xFFFFFFFFu, q0, d);
                    q1 += __shfl_xor_sync(0xFFFFFFFFu, q1, d);
                }
                if (lane < 4) {
                    int c0 = warp_n * 32 + nf * 8 + lane * 2;
                    atomicAdd(&g_stats[c0], s0);
                    atomicAdd(&g_stats[c0 + 1], s1);
                    atomicAdd(&g_stats[HD + c0], q0);
                    atomicAdd(&g_stats[HD + c0 + 1], q1);
                }
            } else {
#pragma unroll
                for (int p = 0; p < 4; p++) {
                    v[p][0] = fmaxf(v[p][0], 0.f);
                    v[p][1] = fmaxf(v[p][1], 0.f);
                }
            }
#pragma unroll
            for (int p = 0; p < 4; p++) {
                int row = r0 + ((p & 1) ? 8 : 0) + ((p >> 1) ? 16 : 0);
                int pi = (p & 1) + (p >> 1) * 2;
                if (row < n) {
                    float2 o = make_float2(v[pi][0], v[pi][1]);
                    *reinterpret_cast<float2*>(Cout + (size_t)row * HD + col) = o;
                }
            }
        }
        __syncthreads();   // A SMEM reuse barrier before next tile's producer
    }
}

// ---------------- segmented pooling (batch is sorted) ---------------------------
__global__ void pool_kernel(const void* __restrict__ batch, int n, int sel) {
    int w = blockIdx.x * (blockDim.x >> 5) + (threadIdx.x >> 5);
    int base = w * 32;
    if (base >= n) return;
    int lane = threadIdx.x & 31;
    int is64 = g_idx64;
    const float* x = sel ? g_xB : g_xA;
    int end = min(base + 32, n);

    float4 acc = make_float4(0.f, 0.f, 0.f, 0.f);
    float cnt = 0.f;
    int cur = (int)load_index(batch, base, is64);
    for (int i = base; i < end; i++) {
        int g = (int)load_index(batch, i, is64);
        if (g != cur) {
            red_add_v4(g_pool + (size_t)cur * HD + lane * 4, acc);
            if (lane == 0) atomicAdd(&g_cnt[cur], cnt);
            acc = make_float4(0.f, 0.f, 0.f, 0.f);
            cnt = 0.f;
            cur = g;
        }
        float4 v = *reinterpret_cast<const float4*>(x + (size_t)i * HD + lane * 4);
        acc.x += v.x; acc.y += v.y; acc.z += v.z; acc.w += v.w;
        cnt += 1.f;
    }
    red_add_v4(g_pool + (size_t)cur * HD + lane * 4, acc);
    if (lane == 0) atomicAdd(&g_cnt[cur], cnt);
}

// ---------------- classifier head ----------------------------------------------
__global__ void head_kernel(const float* __restrict__ Wc,
                            const float* __restrict__ bc,
                            float* __restrict__ out) {
    int g = blockIdx.x;
    int h = threadIdx.x;
    float cnt = g_cnt[g];
    float v = g_pool[g * HD + h] / fmaxf(cnt, 1.f);
    __shared__ float sh[HD];
    for (int c = 0; c < NCLS; c++) {
        sh[h] = v * Wc[h * NCLS + c];
        __syncthreads();
        for (int s = 64; s > 0; s >>= 1) {
            if (h < s) sh[h] += sh[h + s];
            __syncthreads();
        }
        if (h == 0) out[g * NCLS + c] = sh[0] + bc[c];
        __syncthreads();
    }
}

// ---------------- launch ---------------------------------------------------------
extern "C" void kernel_launch(void* const* d_in, const int* in_sizes, int n_in,
                              void* d_out, int out_size) {
    cudaFuncSetAttribute(tgemm_kernel<0>,
                         cudaFuncAttributeMaxDynamicSharedMemorySize, SMEM_SZ);
    cudaFuncSetAttribute(tgemm_kernel<1>,
                         cudaFuncAttributeMaxDynamicSharedMemorySize, SMEM_SZ);
    cudaFuncSetAttribute(tgemm_kernel<2>,
                         cudaFuncAttributeMaxDynamicSharedMemorySize, SMEM_SZ);

    // Detect input ordering: signature order has edge_index (1.6M elems) at [1];
    // setup_inputs dict order has node_centrality (50K) at [1].
    int ix, iei, ib, inc_, iec, iw1, ib1, ig1, ibe1, iw2, ib2, iwc, ibc;
    ix = 0;
    if (n_in >= 13 && in_sizes[1] > 1000000) {
        iei = 1; ib = 2; inc_ = 3; iec = 4;
        iw1 = 5; ib1 = 6; ig1 = 7; ibe1 = 8;
        iw2 = 9; ib2 = 10; iwc = 11; ibc = 12;
    } else {
        inc_ = 1; iec = 2; iw1 = 3; ib1 = 4; ig1 = 5; ibe1 = 6;
        iw2 = 7; ib2 = 8; iwc = 9; ibc = 10; iei = 11; ib = 12;
    }

    const float* x   = (const float*)d_in[ix];
    const void*  ei  = d_in[iei];
    const void*  bat = d_in[ib];
    const float* nc  = (const float*)d_in[inc_];
    const float* ec  = (const float*)d_in[iec];
    const float* W1  = (const float*)d_in[iw1];
    const float* b1  = (const float*)d_in[ib1];
    const float* g1  = (const float*)d_in[ig1];
    const float* be1 = (const float*)d_in[ibe1];
    const float* W2  = (const float*)d_in[iw2];
    const float* b2  = (const float*)d_in[ib2];
    const float* Wc  = (const float*)d_in[iwc];
    const float* bc  = (const float*)d_in[ibc];
    float* out = (float*)d_out;

    int n = in_sizes[ix] / HD;
    int E = in_sizes[iei] / 2;
    int n4 = n * (HD / 4);
    int nchunks = (n + 511) / 512;
    bool use_csr = (E <= EMAX) && (n <= NMAX) && (nchunks <= 128);

    // conv_w + idx-detect + deg/pool/flag-zero in one launch
    int cw_threads = 6 * HD * HD > n + 1 ? 6 * HD * HD : n + 1;
    conv_w_all_kernel<<<(cw_threads + 255) / 256, 256>>>(W1, W2, ei, E, n);

    int tiles = (n + TM - 1) / TM;
    int gemm_grid = tiles < 296 ? tiles : 296;
    int pool_blocks = (n + 255) / 256;   // 8 warps x 32 nodes per block

    if (use_csr) {
        hist_kernel<<<512, 256>>>(ei, E);
        scan_fused_kernel<<<nchunks, 512>>>(n, E, nchunks);
        scatter_kernel<<<512, 256>>>(ei, ec, E);
    }

    int agg_blocks = (n + 7) / 8;
    int edge_blocks = (E + EB - 1) / EB;

    // layer I/O: in x(ext) -> B -> A -> B  (sel<0 means external x)
    int sel_in_tab[3]  = { -1, 1, 0 };
    int sel_out_tab[3] = { 1, 0, 1 };

    for (int l = 0; l < 3; l++) {
        int sel_in = sel_in_tab[l];
        int sel_out = sel_out_tab[l];
        if (use_csr) {
            csr_agg_kernel<<<agg_blocks, 256>>>(n, sel_in, x, nc);
            tgemm_kernel<0><<<gemm_grid, 256, SMEM_SZ>>>(
                nullptr, nullptr, nullptr, b1 + l * HD, n, 0, l, x);
        } else {
            zero_agg_stats_kernel<<<2048, 256>>>(n4);
            edge_agg_kernel<<<edge_blocks, 256>>>(ei, ec, E, sel_in, x);
            tgemm_kernel<2><<<gemm_grid, 256, SMEM_SZ>>>(
                nc, nullptr, nullptr, b1 + l * HD, n, sel_in, l, x);
        }
        tgemm_kernel<1><<<gemm_grid, 256, SMEM_SZ>>>(
            nullptr, g1 + l * HD, be1 + l * HD, b2 + l * HD, n, sel_out, 3 + l, x);
    }

    pool_kernel<<<pool_blocks, 256>>>(bat, n, 1);  // final activations live in g_xB
    head_kernel<<<NG, HD>>>(Wc, bc, out);
}

// round 13
// speedup vs baseline: 1.0234x; 1.0166x over previous
#include <cuda_runtime.h>
#include <cuda_bf16.h>
#include <cstdint>

#define NMAX 50000
#define EMAX 800000
#define HD 128
#define NG 128
#define NCLS 10
#define BPAD 136                      // padded row stride (bf16 elems), 272B: conflict-free ldmatrix
#define EB 128                        // edges staged per block (fallback path)

// ---------------- scratch (device globals; no runtime allocation) -----------
// NOTE: referenced ONLY from device code (selected via int selectors).
// Host-passed &g_x* resolves to host shadow memory (NVLink-C2C, 15-22x slow).
// Harness pointers (d_in[i]) are true device pointers and safe as kernel args.
__device__ float g_xA[NMAX * HD];
__device__ float g_xB[NMAX * HD];
__device__ float g_agg[NMAX * HD];   // fallback (atomic) path only
__device__ float g_h1[NMAX * HD];
__device__ __nv_bfloat16 g_Ahi[NMAX * HD];   // prefused A = x + nc*agg, hi part
__device__ __nv_bfloat16 g_Alo[NMAX * HD];   // lo part (error compensation)
__device__ float g_stats[2 * HD];   // [0:128) col sums, [128:256) col sumsq
__device__ float g_pool[NG * HD];
__device__ float g_cnt[NG];
__device__ int   g_idx64;           // 1 if indices are int64, 0 if int32
// software grid barrier (all CTAs co-resident by construction)
__device__ int   g_bcount;
__device__ int   g_bgen;
// CSR of the (static) edge set, built once per call; (src, w) packed as int2
__device__ int   g_deg[NMAX + 1];
__device__ int   g_off[NMAX + 1];
__device__ int   g_cursor[NMAX];
__device__ int   g_csum[128];       // per-chunk totals (lookback scan)
__device__ int   g_flag[128];       // publish flags (lookback scan)
__device__ int2  g_csr[EMAX];
// pre-split weights in the padded SMEM image: [k][n], row stride BPAD
__device__ __nv_bfloat16 g_Whi[6][HD * BPAD];
__device__ __nv_bfloat16 g_Wlo[6][HD * BPAD];

// ---------------- helpers -----------------------------------------------------
__device__ __forceinline__ uint32_t smem_u32(const void* p) {
    uint32_t a;
    asm("{ .reg .u64 t; cvta.to.shared.u64 t, %1; cvt.u32.u64 %0, t; }"
        : "=r"(a) : "l"(p));
    return a;
}
__device__ __forceinline__ void red_add_v4(float* p, float4 v) {
    asm volatile("red.global.add.v4.f32 [%0], {%1,%2,%3,%4};"
                 :: "l"(p), "f"(v.x), "f"(v.y), "f"(v.z), "f"(v.w)
                 : "memory");
}
__device__ __forceinline__ void cp_async16(uint32_t dst, const void* src) {
    asm volatile("cp.async.ca.shared.global [%0], [%1], 16;"
                 :: "r"(dst), "l"(src) : "memory");
}
__device__ __forceinline__ void cp_async16_zero(uint32_t dst, const void* src) {
    asm volatile("cp.async.ca.shared.global [%0], [%1], 16, 0;"
                 :: "r"(dst), "l"(src) : "memory");
}
__device__ __forceinline__ uint32_t pack_bf(__nv_bfloat16 a, __nv_bfloat16 b) {
    uint16_t ua = *(uint16_t*)&a, ub = *(uint16_t*)&b;
    return (uint32_t)ua | ((uint32_t)ub << 16);
}
__device__ __forceinline__ void split4(float a0, float a1, float a2, float a3,
                                       uint2& hp, uint2& lp) {
    __nv_bfloat16 h0 = __float2bfloat16(a0);
    __nv_bfloat16 h1 = __float2bfloat16(a1);
    __nv_bfloat16 h2 = __float2bfloat16(a2);
    __nv_bfloat16 h3 = __float2bfloat16(a3);
    __nv_bfloat16 l0 = __float2bfloat16(a0 - __bfloat162float(h0));
    __nv_bfloat16 l1 = __float2bfloat16(a1 - __bfloat162float(h1));
    __nv_bfloat16 l2 = __float2bfloat16(a2 - __bfloat162float(h2));
    __nv_bfloat16 l3 = __float2bfloat16(a3 - __bfloat162float(h3));
    hp.x = pack_bf(h0, h1); hp.y = pack_bf(h2, h3);
    lp.x = pack_bf(l0, l1); lp.y = pack_bf(l2, l3);
}
__device__ __forceinline__ void ldmatrix_x4(uint32_t* r, uint32_t addr) {
    asm volatile("ldmatrix.sync.aligned.m8n8.x4.shared.b16 {%0,%1,%2,%3}, [%4];"
                 : "=r"(r[0]), "=r"(r[1]), "=r"(r[2]), "=r"(r[3]) : "r"(addr));
}
__device__ __forceinline__ void ldmatrix_x4_trans(uint32_t* r, uint32_t addr) {
    asm volatile("ldmatrix.sync.aligned.m8n8.x4.trans.shared.b16 {%0,%1,%2,%3}, [%4];"
                 : "=r"(r[0]), "=r"(r[1]), "=r"(r[2]), "=r"(r[3]) : "r"(addr));
}
__device__ __forceinline__ void mma_bf16(float* c, const uint32_t* a, const uint32_t* b) {
    asm volatile(
        "mma.sync.aligned.m16n8k16.row.col.f32.bf16.bf16.f32 "
        "{%0,%1,%2,%3}, {%4,%5,%6,%7}, {%8,%9}, {%0,%1,%2,%3};"
        : "+f"(c[0]), "+f"(c[1]), "+f"(c[2]), "+f"(c[3])
        : "r"(a[0]), "r"(a[1]), "r"(a[2]), "r"(a[3]), "r"(b[0]), "r"(b[1]));
}
__device__ __forceinline__ long long load_index(const void* base, long long off, int is64) {
    if (is64) return ((const long long*)base)[off];
    return (long long)((const int*)base)[off];
}
// layer input select: sel<0 -> external harness pointer, 0 -> g_xA, 1 -> g_xB
__device__ __forceinline__ const float* pick_x(int sel, const float* xext) {
    if (sel < 0) return xext;
    return sel ? g_xB : g_xA;
}
// software grid barrier: valid ONLY when all gridDim.x CTAs are co-resident.
__device__ __forceinline__ void grid_bar() {
    __syncthreads();
    __threadfence();
    if (threadIdx.x == 0) {
        int gen = atomicAdd(&g_bgen, 0);
        if (atomicAdd(&g_bcount, 1) == (int)gridDim.x - 1) {
            atomicExch(&g_bcount, 0);
            atomicAdd(&g_bgen, 1);
        } else {
            while (atomicAdd(&g_bgen, 0) == gen) __nanosleep(64);
        }
    }
    __syncthreads();
    __threadfence();
}

// ---------------- fallback zeroing (atomic path only) --------------------------
__global__ void zero_agg_stats_kernel(int n4) {
    int i = blockIdx.x * blockDim.x + threadIdx.x;
    if (i < 2 * HD) g_stats[i] = 0.f;
    float4 z = make_float4(0.f, 0.f, 0.f, 0.f);
    float4* a = reinterpret_cast<float4*>(g_agg);
    for (int j = i; j < n4; j += gridDim.x * blockDim.x) a[j] = z;
}

// ------- weight pre-split + idx detect + deg/pool/flag zero (one launch) -------
__global__ void conv_w_all_kernel(const float* __restrict__ W1,
                                  const float* __restrict__ W2,
                                  const void* __restrict__ ei, int E, int n_nodes) {
    int i = blockIdx.x * blockDim.x + threadIdx.x;
    if (i == 0) {           // fold index-dtype detection into this launch
        const long long* p64 = (const long long*)ei;
        int ok64 = 1;
        for (int t = 0; t < 16; t++) {
            long long v = p64[t];
            if (v < 0 || v >= (long long)n_nodes) { ok64 = 0; break; }
        }
        if (ok64) {
            for (int t = 0; t < 16; t++) {
                long long v = p64[(size_t)E + t];
                if (v < 0 || v >= (long long)n_nodes) { ok64 = 0; break; }
            }
        }
        g_idx64 = ok64;
    }
    if (i <= n_nodes) g_deg[i] = 0;      // degree-array zeroing
    if (i < NG * HD) g_pool[i] = 0.f;    // pool zeroing
    if (i < NG) g_cnt[i] = 0.f;
    if (i < 128) g_flag[i] = 0;          // lookback-scan flags
    if (i >= 6 * HD * HD) return;
    int slot = i >> 14;
    int j = i & (HD * HD - 1);
    int n = j & 127, k = j >> 7;
    const float* W = (slot < 3) ? (W1 + (size_t)slot * HD * HD)
                                : (W2 + (size_t)(slot - 3) * HD * HD);
    float w = W[k * HD + n];
    __nv_bfloat16 hi = __float2bfloat16(w);
    float lof = w - __bfloat162float(hi);
    g_Whi[slot][k * BPAD + n] = hi;
    g_Wlo[slot][k * BPAD + n] = __float2bfloat16(lof);
}

// ---------------- CSR construction (once per call) -----------------------------
__global__ void hist_kernel(const void* __restrict__ ei, int E) {
    int is64 = g_idx64;
    for (long long e = blockIdx.x * blockDim.x + threadIdx.x; e < E;
         e += (long long)gridDim.x * blockDim.x) {
        int d = (int)load_index(ei, (long long)E + e, is64);
        atomicAdd(&g_deg[d], 1);
    }
}
// Fused exclusive scan over g_deg via decoupled lookback (nchunks <= 128 blocks).
__global__ void scan_fused_kernel(int n, int E, int nchunks) {
    __shared__ int sh[512];
    __shared__ int s_prefix;
    int t = threadIdx.x;
    int chunk = blockIdx.x;
    int i = chunk * 512 + t;
    int v = (i < n) ? g_deg[i] : 0;
    sh[t] = v;
    __syncthreads();
#pragma unroll
    for (int o = 1; o < 512; o <<= 1) {
        int tmp = (t >= o) ? sh[t - o] : 0;
        __syncthreads();
        sh[t] += tmp;
        __syncthreads();
    }
    if (t == 0) {
        g_csum[chunk] = sh[511];
        __threadfence();
        atomicExch(&g_flag[chunk], 1);
        s_prefix = 0;
    }
    __syncthreads();
    if (t < 32) {
        int p = 0;
        for (int c = t; c < chunk; c += 32) {
            while (atomicAdd(&g_flag[c], 0) == 0) { }
            __threadfence();
            p += g_csum[c];
        }
#pragma unroll
        for (int d = 16; d; d >>= 1) p += __shfl_xor_sync(0xFFFFFFFFu, p, d);
        if (t == 0) s_prefix = p;
    }
    __syncthreads();
    if (i < n) {
        int o = sh[t] - v + s_prefix;    // exclusive global offset
        g_off[i] = o;
        g_cursor[i] = o;
    }
    if (chunk == nchunks - 1 && t == 0) g_off[n] = E;
}
__global__ void scatter_kernel(const void* __restrict__ ei,
                               const float* __restrict__ ec, int E) {
    int is64 = g_idx64;
    for (long long e = blockIdx.x * blockDim.x + threadIdx.x; e < E;
         e += (long long)gridDim.x * blockDim.x) {
        int s = (int)load_index(ei, e, is64);
        int d = (int)load_index(ei, (long long)E + e, is64);
        float w = __ldg(ec + e);
        int pos = atomicAdd(&g_cursor[d], 1);
        g_csr[pos] = make_int2(s, __float_as_int(w));
    }
}

// ---------------- CSR aggregation + A prefusion --------------------------------
__global__ __launch_bounds__(256, 4)
void csr_agg_kernel(int n, int sel, const float* __restrict__ xext,
                    const float* __restrict__ nc) {
    if (blockIdx.x == 0 && threadIdx.x < 2 * HD) g_stats[threadIdx.x] = 0.f;
    int v = blockIdx.x * 8 + (threadIdx.x >> 5);
    if (v >= n) return;
    int lane = threadIdx.x & 31;
    const float* x = pick_x(sel, xext);
    int j = g_off[v], end = g_off[v + 1];
    float4 acc = make_float4(0.f, 0.f, 0.f, 0.f);

    for (; j + 8 <= end; j += 8) {
        int2 e[8];
#pragma unroll
        for (int q = 0; q < 8; q++) e[q] = __ldg(g_csr + j + q);
        float4 vv[8];
#pragma unroll
        for (int q = 0; q < 8; q++)
            vv[q] = *reinterpret_cast<const float4*>(x + (size_t)e[q].x * HD + lane * 4);
#pragma unroll
        for (int q = 0; q < 8; q++) {
            float w = __int_as_float(e[q].y);
            acc.x = fmaf(vv[q].x, w, acc.x);
            acc.y = fmaf(vv[q].y, w, acc.y);
            acc.z = fmaf(vv[q].z, w, acc.z);
            acc.w = fmaf(vv[q].w, w, acc.w);
        }
    }
    for (; j < end; j++) {
        int2 e = __ldg(g_csr + j);
        float w = __int_as_float(e.y);
        float4 vv = *reinterpret_cast<const float4*>(x + (size_t)e.x * HD + lane * 4);
        acc.x = fmaf(vv.x, w, acc.x); acc.y = fmaf(vv.y, w, acc.y);
        acc.z = fmaf(vv.z, w, acc.z); acc.w = fmaf(vv.w, w, acc.w);
    }
    float ncv = __ldg(nc + v);
    float4 xv = *reinterpret_cast<const float4*>(x + (size_t)v * HD + lane * 4);
    float a0 = fmaf(acc.x, ncv, xv.x);
    float a1 = fmaf(acc.y, ncv, xv.y);
    float a2 = fmaf(acc.z, ncv, xv.z);
    float a3 = fmaf(acc.w, ncv, xv.w);
    uint2 hp, lp;
    split4(a0, a1, a2, a3, hp, lp);
    size_t bo = ((size_t)v * HD + lane * 4) * 2;
    *reinterpret_cast<uint2*>((char*)g_Ahi + bo) = hp;
    *reinterpret_cast<uint2*>((char*)g_Alo + bo) = lp;
}

// ---------------- fallback edge aggregation (atomic path, E > EMAX) ------------
__global__ __launch_bounds__(256, 4)
void edge_agg_kernel(const void* __restrict__ ei,
                     const float* __restrict__ ec,
                     int E, int sel, const float* __restrict__ xext) {
    __shared__ int s_src[EB];
    __shared__ int s_dst[EB];
    __shared__ float s_w[EB];
    int tid = threadIdx.x, wid = tid >> 5, lane = tid & 31;
    int is64 = g_idx64;
    const float* x = pick_x(sel, xext);

    long long base = (long long)blockIdx.x * EB;
    if (base >= E) return;
    int cnt = min(EB, (int)(E - base));
    if (tid < cnt) {
        s_src[tid] = (int)load_index(ei, base + tid, is64);
        s_dst[tid] = (int)load_index(ei, (long long)E + base + tid, is64);
        s_w[tid] = __ldg(ec + base + tid);
    }
    __syncthreads();

    int e = wid;
    if (e < cnt) {
        int s = s_src[e];
        float4 v = *reinterpret_cast<const float4*>(x + (size_t)s * HD + lane * 4);
        while (true) {
            int en = e + 8;
            float4 vn;
            if (en < cnt) {
                int sn = s_src[en];
                vn = *reinterpret_cast<const float4*>(x + (size_t)sn * HD + lane * 4);
            }
            float w = s_w[e];
            int d = s_dst[e];
            float4 o = make_float4(v.x * w, v.y * w, v.z * w, v.w * w);
            red_add_v4(g_agg + (size_t)d * HD + lane * 4, o);
            if (en >= cnt) break;
            v = vn; e = en;
        }
    }
}

// ---------------- GEMM tile machinery (shared by fused + fallback) -------------
#define TM 64                                // tile rows
#define TILE_A_BYTES (TM * BPAD * 2)         // 17408
#define TILE_B_BYTES (HD * BPAD * 2)         // 34816
#define S_AHI 0
#define S_ALO TILE_A_BYTES
#define S_BHI (2 * TILE_A_BYTES)
#define S_BLO (2 * TILE_A_BYTES + TILE_B_BYTES)
#define SMEM_SZ (2 * TILE_A_BYTES + 2 * TILE_B_BYTES)   // 104448

__device__ __forceinline__ void copy_w_tiles(char* smem, int tid, int slot) {
    const uint4* wh = (const uint4*)g_Whi[slot];
    const uint4* wl = (const uint4*)g_Wlo[slot];
    uint4* dh = (uint4*)(smem + S_BHI);
    uint4* dl = (uint4*)(smem + S_BLO);
    for (int i = tid; i < TILE_B_BYTES / 16; i += 256) {
        dh[i] = wh[i];
        dl[i] = wl[i];
    }
}

__device__ __forceinline__ void mma_tile(uint32_t aBase, uint32_t bBase,
                                         float acc[2][4][4]) {
#pragma unroll
    for (int mf = 0; mf < 2; mf++)
#pragma unroll
        for (int nf = 0; nf < 4; nf++)
#pragma unroll
            for (int q = 0; q < 4; q++) acc[mf][nf][q] = 0.f;
#pragma unroll
    for (int ks = 0; ks < 8; ks++) {
        uint32_t ah[2][4], al[2][4], bh[4][2], bl[4][2];
#pragma unroll
        for (int mf = 0; mf < 2; mf++) {
            uint32_t addr = aBase + mf * 16 * (BPAD * 2) + ks * 32;
            ldmatrix_x4(ah[mf], addr + S_AHI);
            ldmatrix_x4(al[mf], addr + S_ALO);
        }
#pragma unroll
        for (int nb = 0; nb < 2; nb++) {
            uint32_t addr = bBase + ks * 16 * (BPAD * 2) + nb * 32;
            uint32_t rh[4], rl[4];
            ldmatrix_x4_trans(rh, addr + S_BHI);
            ldmatrix_x4_trans(rl, addr + S_BLO);
            bh[2 * nb][0] = rh[0]; bh[2 * nb][1] = rh[1];
            bh[2 * nb + 1][0] = rh[2]; bh[2 * nb + 1][1] = rh[3];
            bl[2 * nb][0] = rl[0]; bl[2 * nb][1] = rl[1];
            bl[2 * nb + 1][0] = rl[2]; bl[2 * nb + 1][1] = rl[3];
        }
#pragma unroll
        for (int mf = 0; mf < 2; mf++)
#pragma unroll
            for (int nf = 0; nf < 4; nf++) {
                mma_bf16(acc[mf][nf], ah[mf], bh[nf]);
                mma_bf16(acc[mf][nf], ah[mf], bl[nf]);
                mma_bf16(acc[mf][nf], al[mf], bh[nf]);
            }
    }
}

// ---------------- FUSED layer GEMM kernel (CSR path) ---------------------------
// Phase 1 (GEMM1): A prefused copy -> h1 = A@W1 + b1, col stats.
// B2 copy during barrier window; software grid barrier; per-CTA BN params.
// Phase 2 (GEMM2): A = relu(BN(h1)) -> out = relu(A@W2 + b2).
__global__ __launch_bounds__(256, 2)
void fused_layer_kernel(const float* __restrict__ gamma,
                        const float* __restrict__ beta,
                        const float* __restrict__ b1,
                        const float* __restrict__ b2,
                        int n, int sel_out, int slot1, int slot2) {
    extern __shared__ char smem[];
    __shared__ __align__(16) float s_scale[HD];
    __shared__ __align__(16) float s_shift[HD];
    uint32_t sb = smem_u32(smem);
    int tid = threadIdx.x, wid = tid >> 5, lane = tid & 31;
    int warp_m = wid & 1;
    int warp_n = wid >> 1;
    int lrow = lane & 15;
    int lblk = (lane >> 4) * 16;
    uint32_t aBase = sb + (warp_m * 32 + lrow) * (BPAD * 2) + lblk;
    uint32_t bBase = sb + lrow * (BPAD * 2) + (warp_n * 32) * 2 + lblk;
    int tiles = (n + TM - 1) / TM;

    // ===== PHASE 1 =====
    copy_w_tiles(smem, tid, slot1);
    for (int t = blockIdx.x; t < tiles; t += gridDim.x) {
        int block_row = t * TM;
        // producer: pure cp.async copy of prefused A
#pragma unroll
        for (int it = 0; it < 8; it++) {
            int f = tid + it * 256;
            int row = f >> 5;
            int c = f & 31;
            int grow = block_row + row;
            bool hi = c < 16;
            int cc = hi ? c : c - 16;
            uint32_t dst = sb + (hi ? S_AHI : S_ALO) + row * (BPAD * 2) + cc * 16;
            if (grow < n) {
                const char* srcp = (const char*)(hi ? g_Ahi : g_Alo)
                                 + ((size_t)grow * HD + cc * 8) * 2;
                cp_async16(dst, srcp);
            } else {
                cp_async16_zero(dst, (const void*)g_Ahi);
            }
        }
        asm volatile("cp.async.commit_group;" ::: "memory");
        asm volatile("cp.async.wait_group 0;" ::: "memory");
        __syncthreads();

        float acc[2][4][4];
        mma_tile(aBase, bBase, acc);

        int r0 = block_row + warp_m * 32 + (lane >> 2);
#pragma unroll
        for (int nf = 0; nf < 4; nf++) {
            int col = warp_n * 32 + nf * 8 + (lane & 3) * 2;
            float bb0 = __ldg(b1 + col), bb1 = __ldg(b1 + col + 1);
            float v[4][2];
#pragma unroll
            for (int mf = 0; mf < 2; mf++) {
                v[mf * 2][0] = acc[mf][nf][0] + bb0;
                v[mf * 2][1] = acc[mf][nf][1] + bb1;
                v[mf * 2 + 1][0] = acc[mf][nf][2] + bb0;
                v[mf * 2 + 1][1] = acc[mf][nf][3] + bb1;
            }
            bool val[4];
            val[0] = r0 < n; val[1] = r0 + 8 < n; val[2] = r0 + 16 < n; val[3] = r0 + 24 < n;
            float s0 = 0.f, s1 = 0.f, q0 = 0.f, q1 = 0.f;
#pragma unroll
            for (int p = 0; p < 4; p++) {
                if (val[p]) {
                    s0 += v[p][0]; q0 += v[p][0] * v[p][0];
                    s1 += v[p][1]; q1 += v[p][1] * v[p][1];
                }
            }
#pragma unroll
            for (int d = 4; d < 32; d <<= 1) {
                s0 += __shfl_xor_sync(0xFFFFFFFFu, s0, d);
                s1 += __shfl_xor_sync(0xFFFFFFFFu, s1, d);
                q0 += __shfl_xor_sync(0xFFFFFFFFu, q0, d);
                q1 += __shfl_xor_sync(0xFFFFFFFFu, q1, d);
            }
            if (lane < 4) {
                int c0 = warp_n * 32 + nf * 8 + lane * 2;
                atomicAdd(&g_stats[c0], s0);
                atomicAdd(&g_stats[c0 + 1], s1);
                atomicAdd(&g_stats[HD + c0], q0);
                atomicAdd(&g_stats[HD + c0 + 1], q1);
            }
#pragma unroll
            for (int p = 0; p < 4; p++) {
                int row = r0 + ((p & 1) ? 8 : 0) + ((p >> 1) ? 16 : 0);
                int pi = (p & 1) + (p >> 1) * 2;
                if (row < n) {
                    float2 o = make_float2(v[pi][0], v[pi][1]);
                    *reinterpret_cast<float2*>(g_h1 + (size_t)row * HD + col) = o;
                }
            }
        }
        __syncthreads();
    }

    // ===== barrier window: load W2 while other CTAs finish phase 1 =====
    copy_w_tiles(smem, tid, slot2);
    grid_bar();

    // BN params from completed stats
    if (tid < HD) {
        float invn = 1.f / (float)n;
        float mu = g_stats[tid] * invn;
        float var = g_stats[HD + tid] * invn - mu * mu;
        float s = gamma[tid] * rsqrtf(var + 1e-5f);
        s_scale[tid] = s;
        s_shift[tid] = beta[tid] - mu * s;
    }
    __syncthreads();

    // ===== PHASE 2 =====
    float* Cout = sel_out ? g_xB : g_xA;
    for (int t = blockIdx.x; t < tiles; t += gridDim.x) {
        int block_row = t * TM;
#pragma unroll 4
        for (int it = 0; it < 8; it++) {
            int f = tid + it * 256;
            int row = f >> 5;
            int kk = (f & 31) << 2;
            int grow = block_row + row;
            int off = row * (BPAD * 2) + kk * 2;
            float4 v = make_float4(0.f, 0.f, 0.f, 0.f);
            if (grow < n) {
                v = *reinterpret_cast<const float4*>(g_h1 + (size_t)grow * HD + kk);
                float4 sc = *reinterpret_cast<const float4*>(s_scale + kk);
                float4 sh = *reinterpret_cast<const float4*>(s_shift + kk);
                v.x = fmaxf(fmaf(v.x, sc.x, sh.x), 0.f);
                v.y = fmaxf(fmaf(v.y, sc.y, sh.y), 0.f);
                v.z = fmaxf(fmaf(v.z, sc.z, sh.z), 0.f);
                v.w = fmaxf(fmaf(v.w, sc.w, sh.w), 0.f);
            }
            uint2 hp, lp;
            split4(v.x, v.y, v.z, v.w, hp, lp);
            *(uint2*)(smem + S_AHI + off) = hp;
            *(uint2*)(smem + S_ALO + off) = lp;
        }
        __syncthreads();

        float acc[2][4][4];
        mma_tile(aBase, bBase, acc);

        int r0 = block_row + warp_m * 32 + (lane >> 2);
#pragma unroll
        for (int nf = 0; nf < 4; nf++) {
            int col = warp_n * 32 + nf * 8 + (lane & 3) * 2;
            float bb0 = __ldg(b2 + col), bb1 = __ldg(b2 + col + 1);
#pragma unroll
            for (int p = 0; p < 4; p++) {
                int row = r0 + ((p & 1) ? 8 : 0) + ((p >> 1) ? 16 : 0);
                int pi = (p & 1) + (p >> 1) * 2;
                int mf = pi >> 1, qo = (pi & 1) * 2;
                if (row < n) {
                    float2 o = make_float2(
                        fmaxf(acc[mf][nf][qo] + bb0, 0.f),
                        fmaxf(acc[mf][nf][qo + 1] + bb1, 0.f));
                    *reinterpret_cast<float2*>(Cout + (size_t)row * HD + col) = o;
                }
            }
        }
        __syncthreads();
    }
}

// ---------------- fallback GEMM kernels (atomic path only) ---------------------
// MODE 1: BN+relu on h1, C = relu(.@W2+b2). MODE 2: A = x + agg*nc, stats.
template <int MODE>
__global__ __launch_bounds__(256, 2)
void tgemm_kernel(const float* __restrict__ nc,
                  const float* __restrict__ gamma,
                  const float* __restrict__ beta,
                  const float* __restrict__ bias,
                  int n, int sel, int slot,
                  const float* __restrict__ xext) {
    extern __shared__ char smem[];
    __shared__ __align__(16) float s_scale[HD];
    __shared__ __align__(16) float s_shift[HD];
    uint32_t sb = smem_u32(smem);
    int tid = threadIdx.x, wid = tid >> 5, lane = tid & 31;
    int warp_m = wid & 1;
    int warp_n = wid >> 1;

    const float* Ain;
    float* Cout;
    if (MODE == 1) { Ain = g_h1; Cout = sel ? g_xB : g_xA; }
    else           { Ain = pick_x(sel, xext); Cout = g_h1; }

    if (MODE == 1) {
        if (tid < HD) {
            float invn = 1.f / (float)n;
            float mu = g_stats[tid] * invn;
            float var = g_stats[HD + tid] * invn - mu * mu;
            float s = gamma[tid] * rsqrtf(var + 1e-5f);
            s_scale[tid] = s;
            s_shift[tid] = beta[tid] - mu * s;
        }
        __syncthreads();
    }
    copy_w_tiles(smem, tid, slot);

    int lrow = lane & 15;
    int lblk = (lane >> 4) * 16;
    uint32_t aBase = sb + (warp_m * 32 + lrow) * (BPAD * 2) + lblk;
    uint32_t bBase = sb + lrow * (BPAD * 2) + (warp_n * 32) * 2 + lblk;

    int tiles = (n + TM - 1) / TM;
    for (int t = blockIdx.x; t < tiles; t += gridDim.x) {
        int block_row = t * TM;
#pragma unroll 4
        for (int it = 0; it < 8; it++) {
            int f = tid + it * 256;
            int row = f >> 5;
            int kk = (f & 31) << 2;
            int grow = block_row + row;
            int off = row * (BPAD * 2) + kk * 2;
            float4 v = make_float4(0.f, 0.f, 0.f, 0.f);
            if (grow < n) {
                v = *reinterpret_cast<const float4*>(Ain + (size_t)grow * HD + kk);
                if (MODE == 2) {
                    float w = __ldg(nc + grow);
                    float4 u = *reinterpret_cast<const float4*>(g_agg + (size_t)grow * HD + kk);
                    v.x = fmaf(u.x, w, v.x);
                    v.y = fmaf(u.y, w, v.y);
                    v.z = fmaf(u.z, w, v.z);
                    v.w = fmaf(u.w, w, v.w);
                } else {
                    float4 sc = *reinterpret_cast<const float4*>(s_scale + kk);
                    float4 sh = *reinterpret_cast<const float4*>(s_shift + kk);
                    v.x = fmaxf(fmaf(v.x, sc.x, sh.x), 0.f);
                    v.y = fmaxf(fmaf(v.y, sc.y, sh.y), 0.f);
                    v.z = fmaxf(fmaf(v.z, sc.z, sh.z), 0.f);
                    v.w = fmaxf(fmaf(v.w, sc.w, sh.w), 0.f);
                }
            }
            uint2 hp, lp;
            split4(v.x, v.y, v.z, v.w, hp, lp);
            *(uint2*)(smem + S_AHI + off) = hp;
            *(uint2*)(smem + S_ALO + off) = lp;
        }
        __syncthreads();

        float acc[2][4][4];
        mma_tile(aBase, bBase, acc);

        int r0 = block_row + warp_m * 32 + (lane >> 2);
#pragma unroll
        for (int nf = 0; nf < 4; nf++) {
            int col = warp_n * 32 + nf * 8 + (lane & 3) * 2;
            float b0 = __ldg(bias + col), b1 = __ldg(bias + col + 1);
            float v[4][2];
#pragma unroll
            for (int mf = 0; mf < 2; mf++) {
                v[mf * 2][0] = acc[mf][nf][0] + b0;
                v[mf * 2][1] = acc[mf][nf][1] + b1;
                v[mf * 2 + 1][0] = acc[mf][nf][2] + b0;
                v[mf * 2 + 1][1] = acc[mf][nf][3] + b1;
            }
            bool val[4];
            val[0] = r0 < n; val[1] = r0 + 8 < n; val[2] = r0 + 16 < n; val[3] = r0 + 24 < n;
            if (MODE != 1) {
                float s0 = 0.f, s1 = 0.f, q0 = 0.f, q1 = 0.f;
#pragma unroll
                for (int p = 0; p < 4; p++) {
                    if (val[p]) {
                        s0 += v[p][0]; q0 += v[p][0] * v[p][0];
                        s1 += v[p][1]; q1 += v[p][1] * v[p][1];
                    }
                }
#pragma unroll
                for (int d = 4; d < 32; d <<= 1) {
                    s0 += __shfl_xor_sync(0xFFFFFFFFu, s0, d);
                    s1 += __shfl_xor_sync(0xFFFFFFFFu, s1, d);
                    q0 += __shfl_xor_sync(0xFFFFFFFFu, q0, d);
                    q1 += __shfl_xor_sync(0xFFFFFFFFu, q1, d);
                }
                if (lane < 4) {
                    int c0 = warp_n * 32 + nf * 8 + lane * 2;
                    atomicAdd(&g_stats[c0], s0);
                    atomicAdd(&g_stats[c0 + 1], s1);
                    atomicAdd(&g_stats[HD + c0], q0);
                    atomicAdd(&g_stats[HD + c0 + 1], q1);
                }
            } else {
#pragma unroll
                for (int p = 0; p < 4; p++) {
                    v[p][0] = fmaxf(v[p][0], 0.f);
                    v[p][1] = fmaxf(v[p][1], 0.f);
                }
            }
#pragma unroll
            for (int p = 0; p < 4; p++) {
                int row = r0 + ((p & 1) ? 8 : 0) + ((p >> 1) ? 16 : 0);
                int pi = (p & 1) + (p >> 1) * 2;
                if (row < n) {
                    float2 o = make_float2(v[pi][0], v[pi][1]);
                    *reinterpret_cast<float2*>(Cout + (size_t)row * HD + col) = o;
                }
            }
        }
        __syncthreads();
    }
}

// ---------------- segmented pooling (batch is sorted) ---------------------------
__global__ void pool_kernel(const void* __restrict__ batch, int n, int sel) {
    int w = blockIdx.x * (blockDim.x >> 5) + (threadIdx.x >> 5);
    int base = w * 32;
    if (base >= n) return;
    int lane = threadIdx.x & 31;
    int is64 = g_idx64;
    const float* x = sel ? g_xB : g_xA;
    int end = min(base + 32, n);

    float4 acc = make_float4(0.f, 0.f, 0.f, 0.f);
    float cnt = 0.f;
    int cur = (int)load_index(batch, base, is64);
    for (int i = base; i < end; i++) {
        int g = (int)load_index(batch, i, is64);
        if (g != cur) {
            red_add_v4(g_pool + (size_t)cur * HD + lane * 4, acc);
            if (lane == 0) atomicAdd(&g_cnt[cur], cnt);
            acc = make_float4(0.f, 0.f, 0.f, 0.f);
            cnt = 0.f;
            cur = g;
        }
        float4 v = *reinterpret_cast<const float4*>(x + (size_t)i * HD + lane * 4);
        acc.x += v.x; acc.y += v.y; acc.z += v.z; acc.w += v.w;
        cnt += 1.f;
    }
    red_add_v4(g_pool + (size_t)cur * HD + lane * 4, acc);
    if (lane == 0) atomicAdd(&g_cnt[cur], cnt);
}

// ---------------- classifier head ----------------------------------------------
__global__ void head_kernel(const float* __restrict__ Wc,
                            const float* __restrict__ bc,
                            float* __restrict__ out) {
    int g = blockIdx.x;
    int h = threadIdx.x;
    float cnt = g_cnt[g];
    float v = g_pool[g * HD + h] / fmaxf(cnt, 1.f);
    __shared__ float sh[HD];
    for (int c = 0; c < NCLS; c++) {
        sh[h] = v * Wc[h * NCLS + c];
        __syncthreads();
        for (int s = 64; s > 0; s >>= 1) {
            if (h < s) sh[h] += sh[h + s];
            __syncthreads();
        }
        if (h == 0) out[g * NCLS + c] = sh[0] + bc[c];
        __syncthreads();
    }
}

// ---------------- launch ---------------------------------------------------------
extern "C" void kernel_launch(void* const* d_in, const int* in_sizes, int n_in,
                              void* d_out, int out_size) {
    cudaFuncSetAttribute(fused_layer_kernel,
                         cudaFuncAttributeMaxDynamicSharedMemorySize, SMEM_SZ);
    cudaFuncSetAttribute(tgemm_kernel<1>,
                         cudaFuncAttributeMaxDynamicSharedMemorySize, SMEM_SZ);
    cudaFuncSetAttribute(tgemm_kernel<2>,
                         cudaFuncAttributeMaxDynamicSharedMemorySize, SMEM_SZ);

    // Detect input ordering: signature order has edge_index (1.6M elems) at [1];
    // setup_inputs dict order has node_centrality (50K) at [1].
    int ix, iei, ib, inc_, iec, iw1, ib1, ig1, ibe1, iw2, ib2, iwc, ibc;
    ix = 0;
    if (n_in >= 13 && in_sizes[1] > 1000000) {
        iei = 1; ib = 2; inc_ = 3; iec = 4;
        iw1 = 5; ib1 = 6; ig1 = 7; ibe1 = 8;
        iw2 = 9; ib2 = 10; iwc = 11; ibc = 12;
    } else {
        inc_ = 1; iec = 2; iw1 = 3; ib1 = 4; ig1 = 5; ibe1 = 6;
        iw2 = 7; ib2 = 8; iwc = 9; ibc = 10; iei = 11; ib = 12;
    }

    const float* x   = (const float*)d_in[ix];
    const void*  ei  = d_in[iei];
    const void*  bat = d_in[ib];
    const float* nc  = (const float*)d_in[inc_];
    const float* ec  = (const float*)d_in[iec];
    const float* W1  = (const float*)d_in[iw1];
    const float* b1  = (const float*)d_in[ib1];
    const float* g1  = (const float*)d_in[ig1];
    const float* be1 = (const float*)d_in[ibe1];
    const float* W2  = (const float*)d_in[iw2];
    const float* b2  = (const float*)d_in[ib2];
    const float* Wc  = (const float*)d_in[iwc];
    const float* bc  = (const float*)d_in[ibc];
    float* out = (float*)d_out;

    int n = in_sizes[ix] / HD;
    int E = in_sizes[iei] / 2;
    int n4 = n * (HD / 4);
    int nchunks = (n + 511) / 512;
    bool use_csr = (E <= EMAX) && (n <= NMAX) && (nchunks <= 128);

    // conv_w + idx-detect + deg/pool/flag-zero in one launch
    int cw_threads = 6 * HD * HD > n + 1 ? 6 * HD * HD : n + 1;
    conv_w_all_kernel<<<(cw_threads + 255) / 256, 256>>>(W1, W2, ei, E, n);

    int tiles = (n + TM - 1) / TM;
    int gemm_grid = tiles < 296 ? tiles : 296;   // <=2 CTAs/SM: all co-resident
    int pool_blocks = (n + 255) / 256;

    if (use_csr) {
        hist_kernel<<<512, 256>>>(ei, E);
        scan_fused_kernel<<<nchunks, 512>>>(n, E, nchunks);
        scatter_kernel<<<512, 256>>>(ei, ec, E);
    }

    int agg_blocks = (n + 7) / 8;
    int edge_blocks = (E + EB - 1) / EB;

    // layer I/O: in x(ext) -> B -> A -> B  (sel<0 means external x)
    int sel_in_tab[3]  = { -1, 1, 0 };
    int sel_out_tab[3] = { 1, 0, 1 };

    for (int l = 0; l < 3; l++) {
        int sel_in = sel_in_tab[l];
        int sel_out = sel_out_tab[l];
        if (use_csr) {
            csr_agg_kernel<<<agg_blocks, 256>>>(n, sel_in, x, nc);
            fused_layer_kernel<<<gemm_grid, 256, SMEM_SZ>>>(
                g1 + l * HD, be1 + l * HD, b1 + l * HD, b2 + l * HD,
                n, sel_out, l, 3 + l);
        } else {
            zero_agg_stats_kernel<<<2048, 256>>>(n4);
            edge_agg_kernel<<<edge_blocks, 256>>>(ei, ec, E, sel_in, x);
            tgemm_kernel<2><<<gemm_grid, 256, SMEM_SZ>>>(
                nc, nullptr, nullptr, b1 + l * HD, n, sel_in, l, x);
            tgemm_kernel<1><<<gemm_grid, 256, SMEM_SZ>>>(
                nullptr, g1 + l * HD, be1 + l * HD, b2 + l * HD, n, sel_out, 3 + l, x);
        }
    }

    pool_kernel<<<pool_blocks, 256>>>(bat, n, 1);  // final activations live in g_xB
    head_kernel<<<NG, HD>>>(Wc, bc, out);
}